// round 2
// baseline (speedup 1.0000x reference)
#include <cuda_runtime.h>

// ---------------------------------------------------------------------------
// Problem constants (shapes fixed by the dataset)
// ---------------------------------------------------------------------------
#define ND 64          // NODE_DIM
#define ED 64          // EDGE_DIM
#define GD 8           // GEO_DIM
#define GO 32          // GEO_OUT
#define CD 512         // COND_DIM
#define KJ 72          // folded join K = ED + GD
#define MAXN 100000
#define MAXB 64

// Device scratch (allocation-free rule: __device__ globals)
__device__ float g_nproj[MAXN * ED];     // 25.6 MB, L2-resident
__device__ float g_gb[MAXB * 2 * ED];    // gamma(+1) | beta per graph
__device__ float g_wfold[KJ * ED];       // [72][64]: Wx[:64] ; Wg@Wx[64:96]
__device__ float g_bgx[ED];              // bg @ Wx[64:96]

// ---------------------------------------------------------------------------
// f32x2 packed fp32 helpers (Blackwell FFMA2 path — 2x fp32 FMA throughput)
// ---------------------------------------------------------------------------
static __device__ __forceinline__ unsigned long long pack2(float lo, float hi) {
    unsigned long long r;
    asm("mov.b64 %0, {%1, %2};" : "=l"(r) : "f"(lo), "f"(hi));
    return r;
}
static __device__ __forceinline__ void fma2(unsigned long long& d,
                                            unsigned long long a,
                                            unsigned long long b) {
    asm("fma.rn.f32x2 %0, %1, %2, %0;" : "+l"(d) : "l"(a), "l"(b));
}
static __device__ __forceinline__ void unpack2(unsigned long long v, float& lo, float& hi) {
    asm("mov.b64 {%0, %1}, %2;" : "=f"(lo), "=f"(hi) : "l"(v));
}

// ---------------------------------------------------------------------------
// Kernel 1: fold Wx + Wg -> g_wfold / g_bgx
// ---------------------------------------------------------------------------
__global__ void prep_kernel(const float* __restrict__ Wx,
                            const float* __restrict__ Wg,
                            const float* __restrict__ bg) {
    int t = threadIdx.x;
    for (int idx = t; idx < KJ * ED; idx += blockDim.x) {
        int k = idx >> 6;
        int j = idx & 63;
        float v;
        if (k < ED) {
            v = Wx[k * ED + j];
        } else {
            int g = k - ED;
            v = 0.0f;
            #pragma unroll 8
            for (int m = 0; m < GO; m++)
                v = fmaf(Wg[g * GO + m], Wx[(ED + m) * ED + j], v);
        }
        g_wfold[idx] = v;
    }
    for (int j = t; j < ED; j += blockDim.x) {
        float v = 0.0f;
        #pragma unroll 8
        for (int m = 0; m < GO; m++)
            v = fmaf(bg[m], Wx[(ED + m) * ED + j], v);
        g_bgx[j] = v;
    }
}

// ---------------------------------------------------------------------------
// Kernel 2: FiLM table  gb = cond @ Wc + bc, gamma += 1
// ---------------------------------------------------------------------------
__global__ void film_kernel(const float* __restrict__ cond,
                            const float* __restrict__ Wc,
                            const float* __restrict__ bc) {
    __shared__ __align__(16) float sc[CD];
    int b = blockIdx.x;
    int j = threadIdx.x;                      // 128 threads = 2*ED outputs
    for (int i = j; i < CD; i += 128) sc[i] = cond[b * CD + i];
    __syncthreads();
    float acc = bc[j];
    #pragma unroll 8
    for (int k = 0; k < CD; k++)
        acc = fmaf(sc[k], Wc[k * (2 * ED) + j], acc);
    if (j < ED) acc += 1.0f;                  // gamma = gamma + 1
    g_gb[b * (2 * ED) + j] = acc;
}

// ---------------------------------------------------------------------------
// Kernel 3: n_proj = node_feats @ Wn + bn     (f32x2 micro-kernel)
// 64-node tiles, 128 threads, thread tile = 8 nodes x 4 cols
// ---------------------------------------------------------------------------
__global__ void nproj_kernel(const float* __restrict__ nf,
                             const float* __restrict__ Wn,
                             const float* __restrict__ bn,
                             int N) {
    __shared__ __align__(16) float sA[ND * 64];   // transposed: [k][node]
    __shared__ __align__(16) float sW[ND * ED];   // [k][col]
    int t = threadIdx.x;

    for (int i = t; i < ND * ED / 4; i += 128)
        ((float4*)sW)[i] = ((const float4*)Wn)[i];

    const int cg  = (t & 15) * 4;   // col base
    const int ngp = (t >> 4) * 8;   // node base in tile
    float4 bn4 = *(const float4*)(bn + cg);

    int tiles = (N + 63) >> 6;
    for (int tile = blockIdx.x; tile < tiles; tile += gridDim.x) {
        __syncthreads();
        int base = tile << 6;
        {   // transpose-load 64 node rows: thread = (node, half)
            int n = t >> 1, h = t & 1;
            int gn = base + n;
            if (gn < N) {
                const float4* ap = (const float4*)(nf + (size_t)gn * ND + 32 * h);
                #pragma unroll
                for (int q = 0; q < 8; q++) {
                    float4 a = ap[q];
                    int k = 32 * h + 4 * q;
                    sA[(k + 0) * 64 + n] = a.x;
                    sA[(k + 1) * 64 + n] = a.y;
                    sA[(k + 2) * 64 + n] = a.z;
                    sA[(k + 3) * 64 + n] = a.w;
                }
            }
        }
        __syncthreads();

        unsigned long long acc[4][4];
        #pragma unroll
        for (int p = 0; p < 4; p++)
            #pragma unroll
            for (int c = 0; c < 4; c++) acc[p][c] = 0ull;

        const float* aB = sA + ngp;
        const float* wB = sW + cg;
        #pragma unroll 8
        for (int k = 0; k < ND; k++) {
            ulonglong2 aA = *(const ulonglong2*)(aB + k * 64);       // nodes 0..3 (2 pairs)
            ulonglong2 aC = *(const ulonglong2*)(aB + k * 64 + 4);   // nodes 4..7
            float4 w = *(const float4*)(wB + k * ED);
            unsigned long long b0 = pack2(w.x, w.x), b1 = pack2(w.y, w.y);
            unsigned long long b2 = pack2(w.z, w.z), b3 = pack2(w.w, w.w);
            fma2(acc[0][0], aA.x, b0); fma2(acc[0][1], aA.x, b1);
            fma2(acc[0][2], aA.x, b2); fma2(acc[0][3], aA.x, b3);
            fma2(acc[1][0], aA.y, b0); fma2(acc[1][1], aA.y, b1);
            fma2(acc[1][2], aA.y, b2); fma2(acc[1][3], aA.y, b3);
            fma2(acc[2][0], aC.x, b0); fma2(acc[2][1], aC.x, b1);
            fma2(acc[2][2], aC.x, b2); fma2(acc[2][3], aC.x, b3);
            fma2(acc[3][0], aC.y, b0); fma2(acc[3][1], aC.y, b1);
            fma2(acc[3][2], aC.y, b2); fma2(acc[3][3], aC.y, b3);
        }

        #pragma unroll
        for (int p = 0; p < 4; p++) {
            float lo[4], hi[4];
            #pragma unroll
            for (int c = 0; c < 4; c++) unpack2(acc[p][c], lo[c], hi[c]);
            int n0 = base + ngp + 2 * p;
            if (n0 < N) {
                float4 o;
                o.x = lo[0] + bn4.x; o.y = lo[1] + bn4.y;
                o.z = lo[2] + bn4.z; o.w = lo[3] + bn4.w;
                *(float4*)(g_nproj + (size_t)n0 * ED + cg) = o;
            }
            if (n0 + 1 < N) {
                float4 o;
                o.x = hi[0] + bn4.x; o.y = hi[1] + bn4.y;
                o.z = hi[2] + bn4.z; o.w = hi[3] + bn4.w;
                *(float4*)(g_nproj + (size_t)(n0 + 1) * ED + cg) = o;
            }
        }
    }
}

// ---------------------------------------------------------------------------
// Kernel 4: main fused edge kernel
// 64-edge tiles, 128 threads. Gather src*dst + geo transposed into smem
// (K-major, K=72), then 8-edge x 4-col f32x2 register GEMM, FiLM+relu epilogue.
// NOTE: edge_index / edge_batch_ids arrive as int32 (harness converts int64).
// ---------------------------------------------------------------------------
__global__ void edge_kernel(const int* __restrict__ eidx,
                            const float* __restrict__ egeo,
                            const int* __restrict__ ebid,
                            float* __restrict__ out,
                            int E) {
    __shared__ __align__(16) float sNJ[KJ * 64];   // [k][edge]
    __shared__ __align__(16) float sW[KJ * ED];    // [k][col]
    __shared__ int   sBid[64];
    int t = threadIdx.x;

    for (int i = t; i < KJ * ED / 4; i += 128)
        ((float4*)sW)[i] = ((const float4*)g_wfold)[i];

    const int cg  = (t & 15) * 4;    // col base
    const int egp = (t >> 4) * 8;    // edge base in tile
    float4 bgx4 = *(const float4*)(g_bgx + cg);

    int tiles = (E + 63) >> 6;
    for (int tile = blockIdx.x; tile < tiles; tile += gridDim.x) {
        __syncthreads();
        int base = tile << 6;
        {   // n_join gather: thread = (edge, half-of-64-dims)
            int e = t >> 1, h = t & 1;
            int ge = base + e;
            if (ge < E) {
                int s = eidx[ge];
                int d = eidx[E + ge];
                const float4* sp = (const float4*)(g_nproj + (size_t)s * ED + 32 * h);
                const float4* dp = (const float4*)(g_nproj + (size_t)d * ED + 32 * h);
                #pragma unroll
                for (int q = 0; q < 8; q++) {
                    float4 a = sp[q];
                    float4 b = dp[q];
                    int k = 32 * h + 4 * q;
                    sNJ[(k + 0) * 64 + e] = a.x * b.x;
                    sNJ[(k + 1) * 64 + e] = a.y * b.y;
                    sNJ[(k + 2) * 64 + e] = a.z * b.z;
                    sNJ[(k + 3) * 64 + e] = a.w * b.w;
                }
            }
            // geo rows 64..71: thread = (edge, quad)
            int e2 = t & 63, q2 = t >> 6;
            int ge2 = base + e2;
            if (ge2 < E) {
                float4 g = *(const float4*)(egeo + (size_t)ge2 * GD + 4 * q2);
                int k = ED + 4 * q2;
                sNJ[(k + 0) * 64 + e2] = g.x;
                sNJ[(k + 1) * 64 + e2] = g.y;
                sNJ[(k + 2) * 64 + e2] = g.z;
                sNJ[(k + 3) * 64 + e2] = g.w;
            }
            if (t < 64) {
                int ge3 = base + t;
                sBid[t] = (ge3 < E) ? ebid[ge3] : 0;
            }
        }
        __syncthreads();

        unsigned long long acc[4][4];
        #pragma unroll
        for (int p = 0; p < 4; p++)
            #pragma unroll
            for (int c = 0; c < 4; c++) acc[p][c] = 0ull;

        const float* aB = sNJ + egp;
        const float* wB = sW + cg;
        #pragma unroll 8
        for (int k = 0; k < KJ; k++) {
            ulonglong2 aA = *(const ulonglong2*)(aB + k * 64);       // edges 0..3
            ulonglong2 aC = *(const ulonglong2*)(aB + k * 64 + 4);   // edges 4..7
            float4 w = *(const float4*)(wB + k * ED);
            unsigned long long b0 = pack2(w.x, w.x), b1 = pack2(w.y, w.y);
            unsigned long long b2 = pack2(w.z, w.z), b3 = pack2(w.w, w.w);
            fma2(acc[0][0], aA.x, b0); fma2(acc[0][1], aA.x, b1);
            fma2(acc[0][2], aA.x, b2); fma2(acc[0][3], aA.x, b3);
            fma2(acc[1][0], aA.y, b0); fma2(acc[1][1], aA.y, b1);
            fma2(acc[1][2], aA.y, b2); fma2(acc[1][3], aA.y, b3);
            fma2(acc[2][0], aC.x, b0); fma2(acc[2][1], aC.x, b1);
            fma2(acc[2][2], aC.x, b2); fma2(acc[2][3], aC.x, b3);
            fma2(acc[3][0], aC.y, b0); fma2(acc[3][1], aC.y, b1);
            fma2(acc[3][2], aC.y, b2); fma2(acc[3][3], aC.y, b3);
        }

        // Epilogue: x += bgx; relu(x*gamma + beta); float4 stores
        #pragma unroll
        for (int p = 0; p < 4; p++) {
            float lo[4], hi[4];
            #pragma unroll
            for (int c = 0; c < 4; c++) unpack2(acc[p][c], lo[c], hi[c]);
            #pragma unroll
            for (int h2 = 0; h2 < 2; h2++) {
                int e  = egp + 2 * p + h2;
                int ge = base + e;
                if (ge >= E) continue;
                int bid = sBid[e];
                float4 gam = *(const float4*)(g_gb + bid * (2 * ED) + cg);
                float4 bet = *(const float4*)(g_gb + bid * (2 * ED) + ED + cg);
                float x0 = (h2 ? hi[0] : lo[0]) + bgx4.x;
                float x1 = (h2 ? hi[1] : lo[1]) + bgx4.y;
                float x2 = (h2 ? hi[2] : lo[2]) + bgx4.z;
                float x3 = (h2 ? hi[3] : lo[3]) + bgx4.w;
                float4 o;
                o.x = fmaxf(fmaf(x0, gam.x, bet.x), 0.0f);
                o.y = fmaxf(fmaf(x1, gam.y, bet.y), 0.0f);
                o.z = fmaxf(fmaf(x2, gam.z, bet.z), 0.0f);
                o.w = fmaxf(fmaf(x3, gam.w, bet.w), 0.0f);
                *(float4*)(out + (size_t)ge * ED + cg) = o;
            }
        }
    }
}

// ---------------------------------------------------------------------------
// Launch
// ---------------------------------------------------------------------------
extern "C" void kernel_launch(void* const* d_in, const int* in_sizes, int n_in,
                              void* d_out, int out_size) {
    const float* nf   = (const float*)d_in[0];
    const int*   eidx = (const int*)d_in[1];     // int64 in ref -> int32 in harness
    const float* egeo = (const float*)d_in[2];
    const float* cond = (const float*)d_in[3];
    const int*   ebid = (const int*)d_in[4];     // int64 in ref -> int32 in harness
    const float* Wn   = (const float*)d_in[5];
    const float* bn   = (const float*)d_in[6];
    const float* Wg   = (const float*)d_in[7];
    const float* bg   = (const float*)d_in[8];
    const float* Wc   = (const float*)d_in[9];
    const float* bc   = (const float*)d_in[10];
    const float* Wx   = (const float*)d_in[11];

    int N = in_sizes[0] / ND;      // nodes
    int E = in_sizes[2] / GD;      // edges
    int B = in_sizes[3] / CD;      // graphs

    prep_kernel<<<1, 256>>>(Wx, Wg, bg);
    film_kernel<<<B, 128>>>(cond, Wc, bc);

    int ntiles = (N + 63) >> 6;
    int ngrid  = ntiles < 888 ? ntiles : 888;
    nproj_kernel<<<ngrid, 128>>>(nf, Wn, bn, N);

    int etiles = (E + 63) >> 6;
    int egrid  = etiles < 888 ? etiles : 888;
    edge_kernel<<<egrid, 128>>>(eidx, egeo, ebid, (float*)d_out, E);
}

// round 3
// speedup vs baseline: 1.1257x; 1.1257x over previous
#include <cuda_runtime.h>

#define ND 64
#define ED 64
#define GD 8
#define GO 32
#define CD 512
#define KJ 72          // folded join K = ED + GD
#define MAXN 100000
#define MAXB 64

#define SJ 88          // edge-major smem row stride (words) for edge kernel
#define SN 72          // node-major smem row stride (words) for nproj kernel

// Device scratch (allocation-free rule: __device__ globals)
__device__ float g_nproj[MAXN * ED];     // 25.6 MB, L2-resident
__device__ float g_gb[MAXB * 2 * ED];    // gamma(+1) | beta per graph
__device__ float g_wfold[KJ * ED];       // [72][64]: Wx[:64] ; Wg@Wx[64:96]
__device__ float g_bgx[ED];              // bg @ Wx[64:96]

// ---------------- f32x2 helpers (Blackwell FFMA2) --------------------------
static __device__ __forceinline__ unsigned long long pack2(float lo, float hi) {
    unsigned long long r;
    asm("mov.b64 %0, {%1, %2};" : "=l"(r) : "f"(lo), "f"(hi));
    return r;
}
static __device__ __forceinline__ void fma2(unsigned long long& d,
                                            unsigned long long a,
                                            unsigned long long b) {
    asm("fma.rn.f32x2 %0, %1, %2, %0;" : "+l"(d) : "l"(a), "l"(b));
}
static __device__ __forceinline__ void unpack2(unsigned long long v, float& lo, float& hi) {
    asm("mov.b64 {%0, %1}, %2;" : "=f"(lo), "=f"(hi) : "l"(v));
}

// ---------------- Kernel 1: fold Wx + Wg -----------------------------------
__global__ void prep_kernel(const float* __restrict__ Wx,
                            const float* __restrict__ Wg,
                            const float* __restrict__ bg) {
    int t = threadIdx.x;
    for (int idx = t; idx < KJ * ED; idx += blockDim.x) {
        int k = idx >> 6, j = idx & 63;
        float v;
        if (k < ED) {
            v = Wx[k * ED + j];
        } else {
            int g = k - ED;
            v = 0.0f;
            #pragma unroll 8
            for (int m = 0; m < GO; m++)
                v = fmaf(Wg[g * GO + m], Wx[(ED + m) * ED + j], v);
        }
        g_wfold[idx] = v;
    }
    for (int j = t; j < ED; j += blockDim.x) {
        float v = 0.0f;
        #pragma unroll 8
        for (int m = 0; m < GO; m++)
            v = fmaf(bg[m], Wx[(ED + m) * ED + j], v);
        g_bgx[j] = v;
    }
}

// ---------------- Kernel 2: FiLM table -------------------------------------
__global__ void film_kernel(const float* __restrict__ cond,
                            const float* __restrict__ Wc,
                            const float* __restrict__ bc) {
    __shared__ __align__(16) float sc[CD];
    int b = blockIdx.x;
    int j = threadIdx.x;
    for (int i = j; i < CD; i += 128) sc[i] = cond[b * CD + i];
    __syncthreads();
    float acc = bc[j];
    #pragma unroll 8
    for (int k = 0; k < CD; k++)
        acc = fmaf(sc[k], Wc[k * (2 * ED) + j], acc);
    if (j < ED) acc += 1.0f;
    g_gb[b * (2 * ED) + j] = acc;
}

// ---------------- Kernel 3: n_proj = nf @ Wn + bn --------------------------
// 128-node tiles, 128 threads; thread = 8 nodes x 8 cols, col-paired f32x2.
// Node-major smem with XOR-8 k-chunk swizzle (conflict-free GEMM loads).
__global__ void __launch_bounds__(128)
nproj_kernel(const float* __restrict__ nf,
             const float* __restrict__ Wn,
             const float* __restrict__ bn,
             int N) {
    extern __shared__ __align__(16) char smem_raw[];
    float* sW = (float*)smem_raw;                 // [64][64] k-major
    float* sA = sW + ND * ED;                     // [128][SN] node-major

    int t = threadIdx.x;
    for (int i = t; i < ND * ED / 4; i += 128)
        ((float4*)sW)[i] = ((const float4*)Wn)[i];

    const int cg  = (t & 7) * 8;    // col base (8 cols)
    const int m   = t >> 3;         // node-group 0..15
    const int egp = m * 8;          // node base in tile
    const int sw  = 8 * (m & 3);    // k swizzle for this thread's reads
    const int w   = t >> 5, lane = t & 31;

    float4 bn0 = *(const float4*)(bn + cg);
    float4 bn1 = *(const float4*)(bn + cg + 4);

    int tiles = (N + 127) >> 7;
    for (int tile = blockIdx.x; tile < tiles; tile += gridDim.x) {
        int base = tile << 7;
        __syncthreads();
        // cooperative fill: 4 nodes x 8 sub-lanes per warp pass
        #pragma unroll
        for (int p = 0; p < 8; p++) {
            int nl  = w * 32 + p * 4 + (lane >> 3);
            int sub = lane & 7;
            int gn  = base + nl;
            float4 v0 = {0,0,0,0}, v1 = {0,0,0,0};
            if (gn < N) {
                const float4* rp = (const float4*)(nf + (size_t)gn * ND);
                v0 = rp[sub * 2];
                v1 = rp[sub * 2 + 1];
            }
            int kb = 8 * (sub ^ ((nl >> 3) & 3));
            float4* dp = (float4*)(sA + nl * SN + kb);
            dp[0] = v0; dp[1] = v1;
        }
        __syncthreads();

        unsigned long long acc[8][4];
        #pragma unroll
        for (int i = 0; i < 8; i++)
            #pragma unroll
            for (int c = 0; c < 4; c++) acc[i][c] = 0ull;

        const float* aB = sA + egp * SN;
        const float* wB = sW + cg;
        #pragma unroll 8
        for (int k = 0; k < ND; k++) {
            int ka = k ^ sw;
            ulonglong2 w01 = *(const ulonglong2*)(wB + k * ED);
            ulonglong2 w23 = *(const ulonglong2*)(wB + k * ED + 4);
            float a[8];
            #pragma unroll
            for (int i = 0; i < 8; i++) a[i] = aB[i * SN + ka];
            #pragma unroll
            for (int i = 0; i < 8; i++) {
                unsigned long long ap = pack2(a[i], a[i]);
                fma2(acc[i][0], ap, w01.x);
                fma2(acc[i][1], ap, w01.y);
                fma2(acc[i][2], ap, w23.x);
                fma2(acc[i][3], ap, w23.y);
            }
        }

        #pragma unroll
        for (int i = 0; i < 8; i++) {
            int gn = base + egp + i;
            if (gn >= N) continue;
            float x[8];
            unpack2(acc[i][0], x[0], x[1]);
            unpack2(acc[i][1], x[2], x[3]);
            unpack2(acc[i][2], x[4], x[5]);
            unpack2(acc[i][3], x[6], x[7]);
            float4 o0 = { x[0] + bn0.x, x[1] + bn0.y, x[2] + bn0.z, x[3] + bn0.w };
            float4 o1 = { x[4] + bn1.x, x[5] + bn1.y, x[6] + bn1.z, x[7] + bn1.w };
            float4* op = (float4*)(g_nproj + (size_t)gn * ED + cg);
            op[0] = o0; op[1] = o1;
        }
    }
}

// ---------------- Kernel 4: main fused edge kernel -------------------------
// 128-edge tiles, 128 threads; thread = 8 edges x 8 cols, col-paired f32x2.
// Cooperative gather (8 lanes/row) -> edge-major swizzled smem -> GEMM K=72.
__global__ void __launch_bounds__(128)
edge_kernel(const int* __restrict__ eidx,
            const float* __restrict__ egeo,
            const int* __restrict__ ebid,
            float* __restrict__ out,
            int E) {
    extern __shared__ __align__(16) char smem_raw[];
    float* sW  = (float*)smem_raw;                // [72][64] k-major
    float* sNJ = sW + KJ * ED;                    // [128][SJ] edge-major
    int*  sIs  = (int*)(sNJ + 128 * SJ);
    int*  sId  = sIs + 128;
    int*  sBid = sId + 128;

    int t = threadIdx.x;
    for (int i = t; i < KJ * ED / 4; i += 128)
        ((float4*)sW)[i] = ((const float4*)g_wfold)[i];

    const int cg  = (t & 7) * 8;
    const int m   = t >> 3;
    const int egp = m * 8;
    const int sw  = 8 * (m & 3);
    const int w   = t >> 5, lane = t & 31;

    float4 bgx0 = *(const float4*)(g_bgx + cg);
    float4 bgx1 = *(const float4*)(g_bgx + cg + 4);

    int tiles = (E + 127) >> 7;
    for (int tile = blockIdx.x; tile < tiles; tile += gridDim.x) {
        int base = tile << 7;
        __syncthreads();
        {
            int ge = base + t;
            bool ok = ge < E;
            sIs[t]  = ok ? eidx[ge]     : 0;
            sId[t]  = ok ? eidx[E + ge] : 0;
            sBid[t] = ok ? ebid[ge]     : 0;
        }
        __syncthreads();

        // cooperative gather + product: 4 edges x 8 sub-lanes per warp pass
        #pragma unroll
        for (int p = 0; p < 8; p++) {
            int el  = w * 32 + p * 4 + (lane >> 3);
            int sub = lane & 7;
            if (base + el < E) {
                int s = sIs[el];
                int d = sId[el];
                const float4* sp = (const float4*)(g_nproj + (size_t)s * ED);
                const float4* dp = (const float4*)(g_nproj + (size_t)d * ED);
                float4 a0 = sp[sub * 2],     a1 = sp[sub * 2 + 1];
                float4 b0 = dp[sub * 2],     b1 = dp[sub * 2 + 1];
                float4 p0 = { a0.x*b0.x, a0.y*b0.y, a0.z*b0.z, a0.w*b0.w };
                float4 p1 = { a1.x*b1.x, a1.y*b1.y, a1.z*b1.z, a1.w*b1.w };
                int kb = 8 * (sub ^ ((el >> 3) & 3));
                float4* q = (float4*)(sNJ + el * SJ + kb);
                q[0] = p0; q[1] = p1;
            }
        }
        // geo rows k=64..71 (stored unswizzled)
        {
            int ge = base + t;
            if (ge < E) {
                const float4* gp = (const float4*)(egeo + (size_t)ge * GD);
                float4 g0 = gp[0], g1 = gp[1];
                float4* q = (float4*)(sNJ + t * SJ + ED);
                q[0] = g0; q[1] = g1;
            }
        }
        __syncthreads();

        unsigned long long acc[8][4];
        #pragma unroll
        for (int i = 0; i < 8; i++)
            #pragma unroll
            for (int c = 0; c < 4; c++) acc[i][c] = 0ull;

        const float* aB = sNJ + egp * SJ;
        const float* wB = sW + cg;
        #pragma unroll 8
        for (int k = 0; k < ED; k++) {          // swizzled part k<64
            int ka = k ^ sw;
            ulonglong2 w01 = *(const ulonglong2*)(wB + k * ED);
            ulonglong2 w23 = *(const ulonglong2*)(wB + k * ED + 4);
            float a[8];
            #pragma unroll
            for (int i = 0; i < 8; i++) a[i] = aB[i * SJ + ka];
            #pragma unroll
            for (int i = 0; i < 8; i++) {
                unsigned long long ap = pack2(a[i], a[i]);
                fma2(acc[i][0], ap, w01.x);
                fma2(acc[i][1], ap, w01.y);
                fma2(acc[i][2], ap, w23.x);
                fma2(acc[i][3], ap, w23.y);
            }
        }
        #pragma unroll
        for (int k = ED; k < KJ; k++) {         // geo rows, unswizzled
            ulonglong2 w01 = *(const ulonglong2*)(wB + k * ED);
            ulonglong2 w23 = *(const ulonglong2*)(wB + k * ED + 4);
            float a[8];
            #pragma unroll
            for (int i = 0; i < 8; i++) a[i] = aB[i * SJ + k];
            #pragma unroll
            for (int i = 0; i < 8; i++) {
                unsigned long long ap = pack2(a[i], a[i]);
                fma2(acc[i][0], ap, w01.x);
                fma2(acc[i][1], ap, w01.y);
                fma2(acc[i][2], ap, w23.x);
                fma2(acc[i][3], ap, w23.y);
            }
        }

        // Epilogue: x += bgx; relu(x*gamma + beta)
        #pragma unroll
        for (int i = 0; i < 8; i++) {
            int ge = base + egp + i;
            if (ge >= E) continue;
            int bid = sBid[egp + i];
            const float* gb = g_gb + bid * (2 * ED);
            float4 gm0 = *(const float4*)(gb + cg);
            float4 gm1 = *(const float4*)(gb + cg + 4);
            float4 bt0 = *(const float4*)(gb + ED + cg);
            float4 bt1 = *(const float4*)(gb + ED + cg + 4);
            float x[8];
            unpack2(acc[i][0], x[0], x[1]);
            unpack2(acc[i][1], x[2], x[3]);
            unpack2(acc[i][2], x[4], x[5]);
            unpack2(acc[i][3], x[6], x[7]);
            float4 o0, o1;
            o0.x = fmaxf(fmaf(x[0] + bgx0.x, gm0.x, bt0.x), 0.0f);
            o0.y = fmaxf(fmaf(x[1] + bgx0.y, gm0.y, bt0.y), 0.0f);
            o0.z = fmaxf(fmaf(x[2] + bgx0.z, gm0.z, bt0.z), 0.0f);
            o0.w = fmaxf(fmaf(x[3] + bgx0.w, gm0.w, bt0.w), 0.0f);
            o1.x = fmaxf(fmaf(x[4] + bgx1.x, gm1.x, bt1.x), 0.0f);
            o1.y = fmaxf(fmaf(x[5] + bgx1.y, gm1.y, bt1.y), 0.0f);
            o1.z = fmaxf(fmaf(x[6] + bgx1.z, gm1.z, bt1.z), 0.0f);
            o1.w = fmaxf(fmaf(x[7] + bgx1.w, gm1.w, bt1.w), 0.0f);
            float4* op = (float4*)(out + (size_t)ge * ED + cg);
            op[0] = o0; op[1] = o1;
        }
    }
}

// ---------------- Launch ---------------------------------------------------
extern "C" void kernel_launch(void* const* d_in, const int* in_sizes, int n_in,
                              void* d_out, int out_size) {
    const float* nf   = (const float*)d_in[0];
    const int*   eidx = (const int*)d_in[1];
    const float* egeo = (const float*)d_in[2];
    const float* cond = (const float*)d_in[3];
    const int*   ebid = (const int*)d_in[4];
    const float* Wn   = (const float*)d_in[5];
    const float* bn   = (const float*)d_in[6];
    const float* Wg   = (const float*)d_in[7];
    const float* bg   = (const float*)d_in[8];
    const float* Wc   = (const float*)d_in[9];
    const float* bc   = (const float*)d_in[10];
    const float* Wx   = (const float*)d_in[11];

    int N = in_sizes[0] / ND;
    int E = in_sizes[2] / GD;
    int B = in_sizes[3] / CD;

    static int configured = 0;
    int smem_np = (ND * ED + 128 * SN) * 4;                 // 53248
    int smem_eg = (KJ * ED + 128 * SJ) * 4 + 3 * 128 * 4;   // 65024
    if (!configured) {
        cudaFuncSetAttribute(nproj_kernel, cudaFuncAttributeMaxDynamicSharedMemorySize, smem_np);
        cudaFuncSetAttribute(edge_kernel,  cudaFuncAttributeMaxDynamicSharedMemorySize, smem_eg);
        configured = 1;
    }

    prep_kernel<<<1, 256>>>(Wx, Wg, bg);
    film_kernel<<<B, 128>>>(cond, Wc, bc);

    int ntiles = (N + 127) >> 7;
    int ngrid  = ntiles < 444 ? ntiles : 444;
    nproj_kernel<<<ngrid, 128, smem_np>>>(nf, Wn, bn, N);

    int etiles = (E + 127) >> 7;
    int egrid  = etiles < 444 ? etiles : 444;
    edge_kernel<<<egrid, 128, smem_eg>>>(eidx, egeo, ebid, (float*)d_out, E);
}

// round 4
// speedup vs baseline: 1.1450x; 1.0171x over previous
#include <cuda_runtime.h>

#define ND 64
#define ED 64
#define GD 8
#define GO 32
#define CD 512
#define KJ 72          // folded join K = ED + GD
#define MAXN 100000
#define MAXB 64

#define SJ   96        // A smem row stride in words (12 chunks of 8)
#define WROW 144       // paired-W smem row stride in words

// Device scratch (allocation-free rule: __device__ globals)
__device__ float g_nproj[MAXN * ED];
__device__ float g_gb[MAXB * 2 * ED];
__device__ float g_wfold[KJ * ED];
__device__ float g_bgx[ED];

// ---------------- f32x2 helpers -------------------------------------------
static __device__ __forceinline__ void fma2(unsigned long long& d,
                                            unsigned long long a,
                                            unsigned long long b) {
    asm("fma.rn.f32x2 %0, %1, %2, %0;" : "+l"(d) : "l"(a), "l"(b));
}
static __device__ __forceinline__ void unpack2(unsigned long long v, float& lo, float& hi) {
    asm("mov.b64 {%0, %1}, %2;" : "=f"(lo), "=f"(hi) : "l"(v));
}
// bank-spreading permutation for paired-W columns (word offset of col v)
static __device__ __forceinline__ int woff(int v) { return v * 2 + ((v >> 4) << 2); }

// ---------------- Kernel 1: fold Wx + Wg ----------------------------------
__global__ void prep_kernel(const float* __restrict__ Wx,
                            const float* __restrict__ Wg,
                            const float* __restrict__ bg) {
    int t = threadIdx.x;
    for (int idx = t; idx < KJ * ED; idx += blockDim.x) {
        int k = idx >> 6, j = idx & 63;
        float v;
        if (k < ED) {
            v = Wx[k * ED + j];
        } else {
            int g = k - ED;
            v = 0.0f;
            #pragma unroll 8
            for (int m = 0; m < GO; m++)
                v = fmaf(Wg[g * GO + m], Wx[(ED + m) * ED + j], v);
        }
        g_wfold[idx] = v;
    }
    for (int j = t; j < ED; j += blockDim.x) {
        float v = 0.0f;
        #pragma unroll 8
        for (int m = 0; m < GO; m++)
            v = fmaf(bg[m], Wx[(ED + m) * ED + j], v);
        g_bgx[j] = v;
    }
}

// ---------------- Kernel 2: FiLM table ------------------------------------
__global__ void film_kernel(const float* __restrict__ cond,
                            const float* __restrict__ Wc,
                            const float* __restrict__ bc) {
    __shared__ __align__(16) float sc[CD];
    int b = blockIdx.x;
    int j = threadIdx.x;
    for (int i = j; i < CD; i += 128) sc[i] = cond[b * CD + i];
    __syncthreads();
    float acc = bc[j];
    #pragma unroll 8
    for (int k = 0; k < CD; k++)
        acc = fmaf(sc[k], Wc[k * (2 * ED) + j], acc);
    if (j < ED) acc += 1.0f;
    g_gb[b * (2 * ED) + j] = acc;
}

// ---------------- Kernel 3: n_proj = nf @ Wn + bn -------------------------
// 64-node tiles, 128 threads; thread = 8 nodes x 4 cols; K-paired f32x2.
__global__ void __launch_bounds__(128, 3)
nproj_kernel(const float* __restrict__ nf,
             const float* __restrict__ Wn,
             const float* __restrict__ bn,
             int N) {
    extern __shared__ __align__(16) char smem_raw[];
    float* sWp = (float*)smem_raw;             // [32][WROW] paired k-major
    float* sA  = sWp + 32 * WROW;              // [64][SJ]   node-major swizzled

    int t = threadIdx.x;
    // stage paired W: (Wn[2k2][c], Wn[2k2+1][c]) at permuted col offset
    for (int i = t; i < 32 * 64; i += 128) {
        int k2 = i >> 6, c = i & 63;
        float lo = Wn[(2 * k2) * ED + c];
        float hi = Wn[(2 * k2 + 1) * ED + c];
        float* dst = sWp + k2 * WROW + woff(c);
        dst[0] = lo; dst[1] = hi;
    }

    const int cidx = t & 15, m = t >> 4;       // 16 col-groups x 8 node-groups
    const int cg = cidx * 4;
    const int swz = m & 3;
    float4 bn4 = *(const float4*)(bn + cg);

    int tiles = (N + 63) >> 6;
    for (int tile = blockIdx.x; tile < tiles; tile += gridDim.x) {
        int base = tile << 6;
        __syncthreads();
        // fill A: 4 passes x 16 rows, 8 lanes per row
        #pragma unroll
        for (int p = 0; p < 4; p++) {
            int nl  = p * 16 + (t >> 3);
            int sub = t & 7;
            int gn  = base + nl;
            if (gn < N) {
                const float4* rp = (const float4*)(nf + (size_t)gn * ND);
                float4 v0 = rp[sub];
                float4 v1 = rp[sub + 8];
                int rs = (nl >> 3) & 3;
                int c0 = sub >> 1, c1 = 4 + (sub >> 1);
                int o  = 4 * (sub & 1);
                *(float4*)(sA + nl * SJ + ((c0 ^ rs) << 3) + o) = v0;
                *(float4*)(sA + nl * SJ + ((c1 ^ rs) << 3) + o) = v1;
            }
        }
        __syncthreads();

        unsigned long long acc[8][4];
        #pragma unroll
        for (int i = 0; i < 8; i++)
            #pragma unroll
            for (int c = 0; c < 4; c++) acc[i][c] = 0ull;

        const float* aB = sA + (m * 8) * SJ;
        #pragma unroll
        for (int c = 0; c < 8; c++) {          // 8 chunks of 8 k
            int pc = (c ^ swz) << 3;
            #pragma unroll
            for (int half = 0; half < 2; half++) {
                int k2b = c * 4 + half * 2;
                ulonglong2 a[8];
                #pragma unroll
                for (int i = 0; i < 8; i++)
                    a[i] = *(const ulonglong2*)(aB + i * SJ + pc + half * 4);
                const float* w0 = sWp + k2b * WROW;
                const float* w1 = w0 + WROW;
                ulonglong2 w00 = *(const ulonglong2*)(w0 + woff(cg));
                ulonglong2 w01 = *(const ulonglong2*)(w0 + woff(cg + 2));
                ulonglong2 w10 = *(const ulonglong2*)(w1 + woff(cg));
                ulonglong2 w11 = *(const ulonglong2*)(w1 + woff(cg + 2));
                #pragma unroll
                for (int i = 0; i < 8; i++) {
                    fma2(acc[i][0], a[i].x, w00.x);
                    fma2(acc[i][1], a[i].x, w00.y);
                    fma2(acc[i][2], a[i].x, w01.x);
                    fma2(acc[i][3], a[i].x, w01.y);
                    fma2(acc[i][0], a[i].y, w10.x);
                    fma2(acc[i][1], a[i].y, w10.y);
                    fma2(acc[i][2], a[i].y, w11.x);
                    fma2(acc[i][3], a[i].y, w11.y);
                }
            }
        }

        #pragma unroll
        for (int i = 0; i < 8; i++) {
            int gn = base + m * 8 + i;
            if (gn >= N) continue;
            float l0, h0, l1, h1, l2, h2, l3, h3;
            unpack2(acc[i][0], l0, h0);
            unpack2(acc[i][1], l1, h1);
            unpack2(acc[i][2], l2, h2);
            unpack2(acc[i][3], l3, h3);
            float4 o = { l0 + h0 + bn4.x, l1 + h1 + bn4.y,
                         l2 + h2 + bn4.z, l3 + h3 + bn4.w };
            *(float4*)(g_nproj + (size_t)gn * ED + cg) = o;
        }
    }
}

// ---------------- Kernel 4: main fused edge kernel ------------------------
// 64-edge tiles, 128 threads; thread = 8 edges x 4 cols; K-paired f32x2.
__global__ void __launch_bounds__(128, 3)
edge_kernel(const int* __restrict__ eidx,
            const float* __restrict__ egeo,
            const int* __restrict__ ebid,
            float* __restrict__ out,
            int E) {
    extern __shared__ __align__(16) char smem_raw[];
    float* sWp = (float*)smem_raw;             // [36][WROW] paired k-major
    float* sA  = sWp + 36 * WROW;              // [64][SJ]   edge-major swizzled
    int*  sIs  = (int*)(sA + 64 * SJ);
    int*  sId  = sIs + 64;
    int*  sBid = sId + 64;

    int t = threadIdx.x;
    // stage paired folded W
    for (int i = t; i < 36 * 64; i += 128) {
        int k2 = i >> 6, c = i & 63;
        float lo = g_wfold[(2 * k2) * ED + c];
        float hi = g_wfold[(2 * k2 + 1) * ED + c];
        float* dst = sWp + k2 * WROW + woff(c);
        dst[0] = lo; dst[1] = hi;
    }

    const int cidx = t & 15, m = t >> 4;
    const int cg = cidx * 4;
    const int swz = m & 3;
    float4 bgx4 = *(const float4*)(g_bgx + cg);

    int tiles = (E + 63) >> 6;
    for (int tile = blockIdx.x; tile < tiles; tile += gridDim.x) {
        int base = tile << 6;
        __syncthreads();
        if (t < 64) {
            int ge = base + t;
            bool ok = ge < E;
            sIs[t]  = ok ? eidx[ge]     : 0;
            sId[t]  = ok ? eidx[E + ge] : 0;
            sBid[t] = ok ? ebid[ge]     : 0;
        }
        __syncthreads();

        // gather + product: 4 passes x 16 edge-rows, 8 lanes per row
        #pragma unroll
        for (int p = 0; p < 4; p++) {
            int el  = p * 16 + (t >> 3);
            int sub = t & 7;
            if (base + el < E) {
                int s = sIs[el];
                int d = sId[el];
                const float4* sp = (const float4*)(g_nproj + (size_t)s * ED);
                const float4* dp = (const float4*)(g_nproj + (size_t)d * ED);
                float4 a0 = sp[sub],     b0 = dp[sub];
                float4 a1 = sp[sub + 8], b1 = dp[sub + 8];
                float4 p0 = { a0.x*b0.x, a0.y*b0.y, a0.z*b0.z, a0.w*b0.w };
                float4 p1 = { a1.x*b1.x, a1.y*b1.y, a1.z*b1.z, a1.w*b1.w };
                int rs = (el >> 3) & 3;
                int c0 = sub >> 1, c1 = 4 + (sub >> 1);
                int o  = 4 * (sub & 1);
                *(float4*)(sA + el * SJ + ((c0 ^ rs) << 3) + o) = p0;
                *(float4*)(sA + el * SJ + ((c1 ^ rs) << 3) + o) = p1;
            }
        }
        // geo rows (chunk 8): 64 edges x 2 halves
        {
            int el = t >> 1, h = t & 1;
            if (base + el < E) {
                float4 g = *(const float4*)(egeo + (size_t)(base + el) * GD + 4 * h);
                int rs = (el >> 3) & 3;
                *(float4*)(sA + el * SJ + ((8 ^ rs) << 3) + 4 * h) = g;
            }
        }
        __syncthreads();

        unsigned long long acc[8][4];
        #pragma unroll
        for (int i = 0; i < 8; i++)
            #pragma unroll
            for (int c = 0; c < 4; c++) acc[i][c] = 0ull;

        const float* aB = sA + (m * 8) * SJ;
        #pragma unroll
        for (int c = 0; c < 9; c++) {          // 9 chunks of 8 k (incl. geo)
            int pc = (c ^ swz) << 3;
            #pragma unroll
            for (int half = 0; half < 2; half++) {
                int k2b = c * 4 + half * 2;
                ulonglong2 a[8];
                #pragma unroll
                for (int i = 0; i < 8; i++)
                    a[i] = *(const ulonglong2*)(aB + i * SJ + pc + half * 4);
                const float* w0 = sWp + k2b * WROW;
                const float* w1 = w0 + WROW;
                ulonglong2 w00 = *(const ulonglong2*)(w0 + woff(cg));
                ulonglong2 w01 = *(const ulonglong2*)(w0 + woff(cg + 2));
                ulonglong2 w10 = *(const ulonglong2*)(w1 + woff(cg));
                ulonglong2 w11 = *(const ulonglong2*)(w1 + woff(cg + 2));
                #pragma unroll
                for (int i = 0; i < 8; i++) {
                    fma2(acc[i][0], a[i].x, w00.x);
                    fma2(acc[i][1], a[i].x, w00.y);
                    fma2(acc[i][2], a[i].x, w01.x);
                    fma2(acc[i][3], a[i].x, w01.y);
                    fma2(acc[i][0], a[i].y, w10.x);
                    fma2(acc[i][1], a[i].y, w10.y);
                    fma2(acc[i][2], a[i].y, w11.x);
                    fma2(acc[i][3], a[i].y, w11.y);
                }
            }
        }

        // Epilogue: x = lo+hi + bgx; relu(x*gamma + beta)
        #pragma unroll
        for (int i = 0; i < 8; i++) {
            int e  = m * 8 + i;
            int ge = base + e;
            if (ge >= E) continue;
            int bid = sBid[e];
            const float* gb = g_gb + bid * (2 * ED);
            float4 gm = *(const float4*)(gb + cg);
            float4 bt = *(const float4*)(gb + ED + cg);
            float l0, h0, l1, h1, l2, h2, l3, h3;
            unpack2(acc[i][0], l0, h0);
            unpack2(acc[i][1], l1, h1);
            unpack2(acc[i][2], l2, h2);
            unpack2(acc[i][3], l3, h3);
            float x0 = l0 + h0 + bgx4.x;
            float x1 = l1 + h1 + bgx4.y;
            float x2 = l2 + h2 + bgx4.z;
            float x3 = l3 + h3 + bgx4.w;
            float4 o;
            o.x = fmaxf(fmaf(x0, gm.x, bt.x), 0.0f);
            o.y = fmaxf(fmaf(x1, gm.y, bt.y), 0.0f);
            o.z = fmaxf(fmaf(x2, gm.z, bt.z), 0.0f);
            o.w = fmaxf(fmaf(x3, gm.w, bt.w), 0.0f);
            *(float4*)(out + (size_t)ge * ED + cg) = o;
        }
    }
}

// ---------------- Launch --------------------------------------------------
extern "C" void kernel_launch(void* const* d_in, const int* in_sizes, int n_in,
                              void* d_out, int out_size) {
    const float* nf   = (const float*)d_in[0];
    const int*   eidx = (const int*)d_in[1];
    const float* egeo = (const float*)d_in[2];
    const float* cond = (const float*)d_in[3];
    const int*   ebid = (const int*)d_in[4];
    const float* Wn   = (const float*)d_in[5];
    const float* bn   = (const float*)d_in[6];
    const float* Wg   = (const float*)d_in[7];
    const float* bg   = (const float*)d_in[8];
    const float* Wc   = (const float*)d_in[9];
    const float* bc   = (const float*)d_in[10];
    const float* Wx   = (const float*)d_in[11];

    int N = in_sizes[0] / ND;
    int E = in_sizes[2] / GD;
    int B = in_sizes[3] / CD;

    int smem_np = (32 * WROW + 64 * SJ) * 4;               // 42 kB
    int smem_eg = (36 * WROW + 64 * SJ) * 4 + 3 * 64 * 4;  // 46 kB

    prep_kernel<<<1, 256>>>(Wx, Wg, bg);
    film_kernel<<<B, 128>>>(cond, Wc, bc);

    int ntiles = (N + 63) >> 6;
    int ngrid  = ntiles < 444 ? ntiles : 444;
    nproj_kernel<<<ngrid, 128, smem_np>>>(nf, Wn, bn, N);

    int etiles = (E + 63) >> 6;
    int egrid  = etiles < 444 ? etiles : 444;
    edge_kernel<<<egrid, 128, smem_eg>>>(eidx, egeo, ebid, (float*)d_out, E);
}

// round 5
// speedup vs baseline: 1.4679x; 1.2820x over previous
#include <cuda_runtime.h>

#define ND 64
#define ED 64
#define GD 8
#define GO 32
#define CD 512
#define KJ 72          // folded join K = ED + GD
#define MAXN 100000
#define MAXB 64

#define SJ   100       // A smem row stride (words); 4*SJ % 32 == 16 (bank spread)
#define WROW 144       // paired-W smem row stride (words)

__device__ float g_nproj[MAXN * ED];
__device__ float g_gb[MAXB * 2 * ED];
__device__ float g_wfold[KJ * ED];
__device__ float g_bgx[ED];

// ---------------- f32x2 helpers -------------------------------------------
static __device__ __forceinline__ void fma2(unsigned long long& d,
                                            unsigned long long a,
                                            unsigned long long b) {
    asm("fma.rn.f32x2 %0, %1, %2, %0;" : "+l"(d) : "l"(a), "l"(b));
}
static __device__ __forceinline__ void unpack2(unsigned long long v, float& lo, float& hi) {
    asm("mov.b64 {%0, %1}, %2;" : "=f"(lo), "=f"(hi) : "l"(v));
}
static __device__ __forceinline__ int woff(int v) { return v * 2 + ((v >> 4) << 2); }

// 8 FFMA2: one A k-pair (2 k) against 4 columns
static __device__ __forceinline__ void fma_kpair(unsigned long long* acc4,
                                                 ulonglong2 a,
                                                 ulonglong2 w0a, ulonglong2 w0b,
                                                 ulonglong2 w1a, ulonglong2 w1b) {
    fma2(acc4[0], a.x, w0a.x); fma2(acc4[1], a.x, w0a.y);
    fma2(acc4[2], a.x, w0b.x); fma2(acc4[3], a.x, w0b.y);
    fma2(acc4[0], a.y, w1a.x); fma2(acc4[1], a.y, w1a.y);
    fma2(acc4[2], a.y, w1b.x); fma2(acc4[3], a.y, w1b.y);
}
static __device__ __forceinline__ float4 mulc(float4 a, float4 b) {
    return make_float4(a.x * b.x, a.y * b.y, a.z * b.z, a.w * b.w);
}
static __device__ __forceinline__ float4 zero4() { return make_float4(0, 0, 0, 0); }

// ---------------- Kernel 1: prep (block B) + FiLM (blocks 0..B-1) ---------
__global__ void prep_film_kernel(const float* __restrict__ Wx,
                                 const float* __restrict__ Wg,
                                 const float* __restrict__ bg,
                                 const float* __restrict__ cond,
                                 const float* __restrict__ Wc,
                                 const float* __restrict__ bc,
                                 int B) {
    int t = threadIdx.x;
    if ((int)blockIdx.x == B) {
        // fold Wx + Wg
        for (int idx = t; idx < KJ * ED; idx += blockDim.x) {
            int k = idx >> 6, j = idx & 63;
            float v;
            if (k < ED) {
                v = Wx[k * ED + j];
            } else {
                int g = k - ED;
                v = 0.0f;
                #pragma unroll 8
                for (int m = 0; m < GO; m++)
                    v = fmaf(Wg[g * GO + m], Wx[(ED + m) * ED + j], v);
            }
            g_wfold[idx] = v;
        }
        for (int j = t; j < ED; j += blockDim.x) {
            float v = 0.0f;
            #pragma unroll 8
            for (int m = 0; m < GO; m++)
                v = fmaf(bg[m], Wx[(ED + m) * ED + j], v);
            g_bgx[j] = v;
        }
        return;
    }
    // FiLM: 256 threads, split k into two halves, reduce
    __shared__ __align__(16) float sc[CD];
    __shared__ float red[256];
    int b = blockIdx.x;
    for (int i = t; i < CD; i += 256) sc[i] = cond[b * CD + i];
    __syncthreads();
    int j  = t & 127;
    int kh = t >> 7;                 // 0 or 1
    float a0 = 0, a1 = 0, a2 = 0, a3 = 0;
    int kb = kh * 256;
    #pragma unroll 4
    for (int k = 0; k < 256; k += 4) {
        a0 = fmaf(sc[kb + k + 0], Wc[(kb + k + 0) * (2 * ED) + j], a0);
        a1 = fmaf(sc[kb + k + 1], Wc[(kb + k + 1) * (2 * ED) + j], a1);
        a2 = fmaf(sc[kb + k + 2], Wc[(kb + k + 2) * (2 * ED) + j], a2);
        a3 = fmaf(sc[kb + k + 3], Wc[(kb + k + 3) * (2 * ED) + j], a3);
    }
    red[t] = (a0 + a1) + (a2 + a3);
    __syncthreads();
    if (t < 128) {
        float acc = red[t] + red[t + 128] + bc[j];
        if (j < ED) acc += 1.0f;
        g_gb[b * (2 * ED) + j] = acc;
    }
}

// ---------------- Kernel 2: n_proj = nf @ Wn + bn (pipelined) --------------
__global__ void __launch_bounds__(256, 2)
nproj_kernel(const float* __restrict__ nf,
             const float* __restrict__ Wn,
             const float* __restrict__ bn,
             int N) {
    extern __shared__ __align__(16) char smem_raw[];
    float* sWp = (float*)smem_raw;             // [32][WROW]
    float* sA  = sWp + 32 * WROW;              // [64][SJ]

    int t = threadIdx.x;
    for (int i = t; i < 32 * 64; i += 256) {
        int k2 = i >> 6, c = i & 63;
        float lo = Wn[(2 * k2) * ED + c];
        float hi = Wn[(2 * k2 + 1) * ED + c];
        float* dst = sWp + k2 * WROW + woff(c);
        dst[0] = lo; dst[1] = hi;
    }

    const int cidx = t & 15, m = t >> 4;       // 16 col-groups x 16 row-groups
    const int cg   = cidx * 4;
    const int wcol = woff(cg);
    const int swz  = (m >> 1) & 3;
    const int sub  = t & 7;
    const int el0  = t >> 3;                   // 0..31
    const int el1  = 32 + el0;
    const int rs0  = (el0 >> 3) & 3, rs1 = (el1 >> 3) & 3;
    const int c0s  = sub >> 1, c1s = 4 + (sub >> 1), osub = 4 * (sub & 1);
    float4 bn4 = *(const float4*)(bn + cg);

    int tiles = (N + 63) >> 6;
    int step  = gridDim.x;

    float4 st[4];
    {   // prologue: stage rows of tile0
        int nb = (int)blockIdx.x << 6;
        int g0 = nb + el0, g1 = nb + el1;
        if (g0 < N) {
            const float4* rp = (const float4*)(nf + (size_t)g0 * ND);
            st[0] = rp[sub]; st[1] = rp[sub + 8];
        } else { st[0] = zero4(); st[1] = zero4(); }
        if (g1 < N) {
            const float4* rp = (const float4*)(nf + (size_t)g1 * ND);
            st[2] = rp[sub]; st[3] = rp[sub + 8];
        } else { st[2] = zero4(); st[3] = zero4(); }
    }

    for (int tile = blockIdx.x; tile < tiles; tile += step) {
        int base = tile << 6;
        __syncthreads();
        // store staged rows
        *(float4*)(sA + el0 * SJ + ((c0s ^ rs0) << 3) + osub) = st[0];
        *(float4*)(sA + el0 * SJ + ((c1s ^ rs0) << 3) + osub) = st[1];
        *(float4*)(sA + el1 * SJ + ((c0s ^ rs1) << 3) + osub) = st[2];
        *(float4*)(sA + el1 * SJ + ((c1s ^ rs1) << 3) + osub) = st[3];
        // prefetch next tile rows
        {
            int nb = (tile + step) << 6;
            int g0 = nb + el0, g1 = nb + el1;
            if (g0 < N) {
                const float4* rp = (const float4*)(nf + (size_t)g0 * ND);
                st[0] = rp[sub]; st[1] = rp[sub + 8];
            } else { st[0] = zero4(); st[1] = zero4(); }
            if (g1 < N) {
                const float4* rp = (const float4*)(nf + (size_t)g1 * ND);
                st[2] = rp[sub]; st[3] = rp[sub + 8];
            } else { st[2] = zero4(); st[3] = zero4(); }
        }
        __syncthreads();

        unsigned long long acc[4][4] = {};
        const float* aB = sA + (m * 4) * SJ;
        #pragma unroll
        for (int c = 0; c < 8; c++) {
            int pc = (c ^ swz) << 3;
            #pragma unroll
            for (int half = 0; half < 2; half++) {
                int k2b = c * 4 + half * 2;
                ulonglong2 a0 = *(const ulonglong2*)(aB + 0 * SJ + pc + half * 4);
                ulonglong2 a1 = *(const ulonglong2*)(aB + 1 * SJ + pc + half * 4);
                ulonglong2 a2 = *(const ulonglong2*)(aB + 2 * SJ + pc + half * 4);
                ulonglong2 a3 = *(const ulonglong2*)(aB + 3 * SJ + pc + half * 4);
                const float* w0 = sWp + k2b * WROW + wcol;
                const float* w1 = w0 + WROW;
                ulonglong2 w0a = *(const ulonglong2*)(w0);
                ulonglong2 w0b = *(const ulonglong2*)(w0 + 4);
                ulonglong2 w1a = *(const ulonglong2*)(w1);
                ulonglong2 w1b = *(const ulonglong2*)(w1 + 4);
                fma_kpair(acc[0], a0, w0a, w0b, w1a, w1b);
                fma_kpair(acc[1], a1, w0a, w0b, w1a, w1b);
                fma_kpair(acc[2], a2, w0a, w0b, w1a, w1b);
                fma_kpair(acc[3], a3, w0a, w0b, w1a, w1b);
            }
        }

        #pragma unroll
        for (int i = 0; i < 4; i++) {
            int gn = base + m * 4 + i;
            if (gn >= N) continue;
            float l0, h0, l1, h1, l2, h2, l3, h3;
            unpack2(acc[i][0], l0, h0);
            unpack2(acc[i][1], l1, h1);
            unpack2(acc[i][2], l2, h2);
            unpack2(acc[i][3], l3, h3);
            float4 o = { l0 + h0 + bn4.x, l1 + h1 + bn4.y,
                         l2 + h2 + bn4.z, l3 + h3 + bn4.w };
            *(float4*)(g_nproj + (size_t)gn * ED + cg) = o;
        }
    }
}

// ---------------- Kernel 3: main fused edge kernel (pipelined) -------------
__global__ void __launch_bounds__(256, 2)
edge_kernel(const int* __restrict__ eidx,
            const float* __restrict__ egeo,
            const int* __restrict__ ebid,
            float* __restrict__ out,
            int E) {
    extern __shared__ __align__(16) char smem_raw[];
    float* sWp = (float*)smem_raw;             // [36][WROW]
    float* sA  = sWp + 36 * WROW;              // [64][SJ]
    int*  sBid = (int*)(sA + 64 * SJ);         // [64]

    int t = threadIdx.x;
    for (int i = t; i < 36 * 64; i += 256) {
        int k2 = i >> 6, c = i & 63;
        float lo = g_wfold[(2 * k2) * ED + c];
        float hi = g_wfold[(2 * k2 + 1) * ED + c];
        float* dst = sWp + k2 * WROW + woff(c);
        dst[0] = lo; dst[1] = hi;
    }

    const int cidx = t & 15, m = t >> 4;
    const int cg   = cidx * 4;
    const int wcol = woff(cg);
    const int swz  = (m >> 1) & 3;
    const int sub  = t & 7;
    const int el0  = t >> 3;                   // 0..31
    const int el1  = 32 + el0;
    const int rs0  = (el0 >> 3) & 3, rs1 = (el1 >> 3) & 3;
    const int c0s  = sub >> 1, c1s = 4 + (sub >> 1), osub = 4 * (sub & 1);
    const int elg  = t >> 1, hg = t & 1, rsg = (elg >> 3) & 3;   // geo task (t<128)
    float4 bgx4 = *(const float4*)(g_bgx + cg);

    int tiles = (E + 63) >> 6;
    int step  = gridDim.x;

    float4 st[8];                              // raw src/dst rows (2 passes)
    float4 geoS = zero4();
    int ns0, nd0, ns1, nd1;                    // indices for tile+step
    int bidS = 0, nbid = 0;

    {   // prologue
        int nb = (int)blockIdx.x << 6;
        int g0 = nb + el0, g1 = nb + el1;
        int s0 = (g0 < E) ? eidx[g0] : 0;
        int d0 = (g0 < E) ? eidx[E + g0] : 0;
        int s1 = (g1 < E) ? eidx[g1] : 0;
        int d1 = (g1 < E) ? eidx[E + g1] : 0;
        const float4* p;
        p = (const float4*)(g_nproj + (size_t)s0 * ED); st[0] = p[sub]; st[1] = p[sub + 8];
        p = (const float4*)(g_nproj + (size_t)d0 * ED); st[2] = p[sub]; st[3] = p[sub + 8];
        p = (const float4*)(g_nproj + (size_t)s1 * ED); st[4] = p[sub]; st[5] = p[sub + 8];
        p = (const float4*)(g_nproj + (size_t)d1 * ED); st[6] = p[sub]; st[7] = p[sub + 8];
        if (t < 128) {
            int ge = nb + elg;
            geoS = (ge < E) ? *(const float4*)(egeo + (size_t)ge * GD + 4 * hg) : zero4();
        }
        if (t < 64) bidS = (nb + t < E) ? ebid[nb + t] : 0;
        // indices of tile0+step
        int nb2 = ((int)blockIdx.x + step) << 6;
        int h0 = nb2 + el0, h1 = nb2 + el1;
        ns0 = (h0 < E) ? eidx[h0] : 0;
        nd0 = (h0 < E) ? eidx[E + h0] : 0;
        ns1 = (h1 < E) ? eidx[h1] : 0;
        nd1 = (h1 < E) ? eidx[E + h1] : 0;
        if (t < 64) nbid = (nb2 + t < E) ? ebid[nb2 + t] : 0;
    }

    for (int tile = blockIdx.x; tile < tiles; tile += step) {
        int base = tile << 6;
        __syncthreads();
        // ---- store staged tile (product + geo + bid) ----
        {
            float4 p00 = mulc(st[0], st[2]), p01 = mulc(st[1], st[3]);
            float4 p10 = mulc(st[4], st[6]), p11 = mulc(st[5], st[7]);
            *(float4*)(sA + el0 * SJ + ((c0s ^ rs0) << 3) + osub) = p00;
            *(float4*)(sA + el0 * SJ + ((c1s ^ rs0) << 3) + osub) = p01;
            *(float4*)(sA + el1 * SJ + ((c0s ^ rs1) << 3) + osub) = p10;
            *(float4*)(sA + el1 * SJ + ((c1s ^ rs1) << 3) + osub) = p11;
            if (t < 128)
                *(float4*)(sA + elg * SJ + ((8 ^ rsg) << 3) + 4 * hg) = geoS;
            if (t < 64) sBid[t] = bidS;
        }
        // ---- prefetch rows for tile+step (indices already resident) ----
        {
            const float4* p;
            p = (const float4*)(g_nproj + (size_t)ns0 * ED); st[0] = p[sub]; st[1] = p[sub + 8];
            p = (const float4*)(g_nproj + (size_t)nd0 * ED); st[2] = p[sub]; st[3] = p[sub + 8];
            p = (const float4*)(g_nproj + (size_t)ns1 * ED); st[4] = p[sub]; st[5] = p[sub + 8];
            p = (const float4*)(g_nproj + (size_t)nd1 * ED); st[6] = p[sub]; st[7] = p[sub + 8];
            int nb = (tile + step) << 6;
            if (t < 128) {
                int ge = nb + elg;
                geoS = (ge < E) ? *(const float4*)(egeo + (size_t)ge * GD + 4 * hg) : zero4();
            }
            bidS = nbid;
            // ---- prefetch indices for tile+2*step ----
            int nb2 = (tile + 2 * step) << 6;
            int h0 = nb2 + el0, h1 = nb2 + el1;
            ns0 = (h0 < E) ? eidx[h0] : 0;
            nd0 = (h0 < E) ? eidx[E + h0] : 0;
            ns1 = (h1 < E) ? eidx[h1] : 0;
            nd1 = (h1 < E) ? eidx[E + h1] : 0;
            if (t < 64) nbid = (nb2 + t < E) ? ebid[nb2 + t] : 0;
        }
        __syncthreads();

        // ---- GEMM: 4 edges x 4 cols, K = 72 ----
        unsigned long long acc[4][4] = {};
        const float* aB = sA + (m * 4) * SJ;
        #pragma unroll
        for (int c = 0; c < 9; c++) {
            int pc = (c ^ swz) << 3;
            #pragma unroll
            for (int half = 0; half < 2; half++) {
                int k2b = c * 4 + half * 2;
                ulonglong2 a0 = *(const ulonglong2*)(aB + 0 * SJ + pc + half * 4);
                ulonglong2 a1 = *(const ulonglong2*)(aB + 1 * SJ + pc + half * 4);
                ulonglong2 a2 = *(const ulonglong2*)(aB + 2 * SJ + pc + half * 4);
                ulonglong2 a3 = *(const ulonglong2*)(aB + 3 * SJ + pc + half * 4);
                const float* w0 = sWp + k2b * WROW + wcol;
                const float* w1 = w0 + WROW;
                ulonglong2 w0a = *(const ulonglong2*)(w0);
                ulonglong2 w0b = *(const ulonglong2*)(w0 + 4);
                ulonglong2 w1a = *(const ulonglong2*)(w1);
                ulonglong2 w1b = *(const ulonglong2*)(w1 + 4);
                fma_kpair(acc[0], a0, w0a, w0b, w1a, w1b);
                fma_kpair(acc[1], a1, w0a, w0b, w1a, w1b);
                fma_kpair(acc[2], a2, w0a, w0b, w1a, w1b);
                fma_kpair(acc[3], a3, w0a, w0b, w1a, w1b);
            }
        }

        // ---- epilogue: FiLM + relu ----
        #pragma unroll
        for (int i = 0; i < 4; i++) {
            int e  = m * 4 + i;
            int ge = base + e;
            if (ge >= E) continue;
            int bid = sBid[e];
            const float* gb = g_gb + bid * (2 * ED);
            float4 gm = *(const float4*)(gb + cg);
            float4 bt = *(const float4*)(gb + ED + cg);
            float l0, h0, l1, h1, l2, h2, l3, h3;
            unpack2(acc[i][0], l0, h0);
            unpack2(acc[i][1], l1, h1);
            unpack2(acc[i][2], l2, h2);
            unpack2(acc[i][3], l3, h3);
            float x0 = l0 + h0 + bgx4.x;
            float x1 = l1 + h1 + bgx4.y;
            float x2 = l2 + h2 + bgx4.z;
            float x3 = l3 + h3 + bgx4.w;
            float4 o;
            o.x = fmaxf(fmaf(x0, gm.x, bt.x), 0.0f);
            o.y = fmaxf(fmaf(x1, gm.y, bt.y), 0.0f);
            o.z = fmaxf(fmaf(x2, gm.z, bt.z), 0.0f);
            o.w = fmaxf(fmaf(x3, gm.w, bt.w), 0.0f);
            *(float4*)(out + (size_t)ge * ED + cg) = o;
        }
    }
}

// ---------------- Launch ---------------------------------------------------
extern "C" void kernel_launch(void* const* d_in, const int* in_sizes, int n_in,
                              void* d_out, int out_size) {
    const float* nf   = (const float*)d_in[0];
    const int*   eidx = (const int*)d_in[1];
    const float* egeo = (const float*)d_in[2];
    const float* cond = (const float*)d_in[3];
    const int*   ebid = (const int*)d_in[4];
    const float* Wn   = (const float*)d_in[5];
    const float* bn   = (const float*)d_in[6];
    const float* Wg   = (const float*)d_in[7];
    const float* bg   = (const float*)d_in[8];
    const float* Wc   = (const float*)d_in[9];
    const float* bc   = (const float*)d_in[10];
    const float* Wx   = (const float*)d_in[11];

    int N = in_sizes[0] / ND;
    int E = in_sizes[2] / GD;
    int B = in_sizes[3] / CD;

    int smem_np = (32 * WROW + 64 * SJ) * 4;             // 44032 B
    int smem_eg = (36 * WROW + 64 * SJ) * 4 + 64 * 4;    // 46592 B

    prep_film_kernel<<<B + 1, 256>>>(Wx, Wg, bg, cond, Wc, bc, B);

    int ntiles = (N + 63) >> 6;
    int ngrid  = ntiles < 296 ? ntiles : 296;
    nproj_kernel<<<ngrid, 256, smem_np>>>(nf, Wn, bn, N);

    int etiles = (E + 63) >> 6;
    int egrid  = etiles < 296 ? etiles : 296;
    edge_kernel<<<egrid, 256, smem_eg>>>(eidx, egeo, ebid, (float*)d_out, E);
}

// round 8
// speedup vs baseline: 1.4714x; 1.0024x over previous
#include <cuda_runtime.h>

#define ND 64
#define ED 64
#define GD 8
#define GO 32
#define CD 512
#define KJ 72          // folded join K = ED + GD
#define MAXN 100000
#define MAXB 64

#define SJ   100       // A smem row stride (words)
#define WROW 144       // paired-W smem row stride (words)
#define ABUF (64 * SJ) // one A buffer in words

__device__ float g_nproj[MAXN * ED];
__device__ float g_gb[MAXB * 2 * ED];
__device__ float g_wfold[KJ * ED];
__device__ float g_bgx[ED];

// ---------------- f32x2 helpers -------------------------------------------
static __device__ __forceinline__ void fma2(unsigned long long& d,
                                            unsigned long long a,
                                            unsigned long long b) {
    asm("fma.rn.f32x2 %0, %1, %2, %0;" : "+l"(d) : "l"(a), "l"(b));
}
static __device__ __forceinline__ void unpack2(unsigned long long v, float& lo, float& hi) {
    asm("mov.b64 {%0, %1}, %2;" : "=f"(lo), "=f"(hi) : "l"(v));
}
static __device__ __forceinline__ int woff(int v) { return v * 2 + ((v >> 4) << 2); }
static __device__ __forceinline__ int imin(int a, int b) { return a < b ? a : b; }

static __device__ __forceinline__ void fma_kpair(unsigned long long* acc4,
                                                 ulonglong2 a,
                                                 ulonglong2 w0a, ulonglong2 w0b,
                                                 ulonglong2 w1a, ulonglong2 w1b) {
    fma2(acc4[0], a.x, w0a.x); fma2(acc4[1], a.x, w0a.y);
    fma2(acc4[2], a.x, w0b.x); fma2(acc4[3], a.x, w0b.y);
    fma2(acc4[0], a.y, w1a.x); fma2(acc4[1], a.y, w1a.y);
    fma2(acc4[2], a.y, w1b.x); fma2(acc4[3], a.y, w1b.y);
}
static __device__ __forceinline__ float4 mulc(float4 a, float4 b) {
    return make_float4(a.x * b.x, a.y * b.y, a.z * b.z, a.w * b.w);
}

// ---------------------------------------------------------------------------
// Kernel 1: setup (film blocks 0..B-1, prep block B) + pipelined n_proj (all)
// ---------------------------------------------------------------------------
__global__ void __launch_bounds__(256, 2)
setup_nproj_kernel(const float* __restrict__ nf,
                   const float* __restrict__ Wn,
                   const float* __restrict__ bn,
                   int N,
                   const float* __restrict__ Wx,
                   const float* __restrict__ Wg,
                   const float* __restrict__ bg,
                   const float* __restrict__ cond,
                   const float* __restrict__ Wc,
                   const float* __restrict__ bc,
                   int B) {
    extern __shared__ __align__(16) char smem_raw[];
    int t = threadIdx.x;

    // ---- setup phase ----
    if ((int)blockIdx.x < B) {
        float* sc  = (float*)smem_raw;            // [512]
        float* red = sc + CD;                     // [256]
        int b = blockIdx.x;
        for (int i = t; i < CD; i += 256) sc[i] = cond[b * CD + i];
        __syncthreads();
        int j  = t & 127;
        int kb = (t >> 7) * 256;
        float a0 = 0, a1 = 0, a2 = 0, a3 = 0;
        #pragma unroll 4
        for (int k = 0; k < 256; k += 4) {
            a0 = fmaf(sc[kb + k + 0], Wc[(kb + k + 0) * (2 * ED) + j], a0);
            a1 = fmaf(sc[kb + k + 1], Wc[(kb + k + 1) * (2 * ED) + j], a1);
            a2 = fmaf(sc[kb + k + 2], Wc[(kb + k + 2) * (2 * ED) + j], a2);
            a3 = fmaf(sc[kb + k + 3], Wc[(kb + k + 3) * (2 * ED) + j], a3);
        }
        red[t] = (a0 + a1) + (a2 + a3);
        __syncthreads();
        if (t < 128) {
            float acc = red[t] + red[t + 128] + bc[j];
            if (j < ED) acc += 1.0f;
            g_gb[b * (2 * ED) + j] = acc;
        }
    } else if ((int)blockIdx.x == B) {
        for (int idx = t; idx < KJ * ED; idx += 256) {
            int k = idx >> 6, j = idx & 63;
            float v;
            if (k < ED) {
                v = Wx[k * ED + j];
            } else {
                int g = k - ED;
                v = 0.0f;
                #pragma unroll 8
                for (int m = 0; m < GO; m++)
                    v = fmaf(Wg[g * GO + m], Wx[(ED + m) * ED + j], v);
            }
            g_wfold[idx] = v;
        }
        for (int j = t; j < ED; j += 256) {
            float v = 0.0f;
            #pragma unroll 8
            for (int m = 0; m < GO; m++)
                v = fmaf(bg[m], Wx[(ED + m) * ED + j], v);
            g_bgx[j] = v;
        }
    }
    __syncthreads();   // smem reuse barrier

    // ---- n_proj phase: double-buffered pipelined GEMM ----
    float* sWp = (float*)smem_raw;             // [32][WROW]
    float* sA  = sWp + 32 * WROW;              // [2][64][SJ]

    for (int i = t; i < 32 * 64; i += 256) {
        int k2 = i >> 6, c = i & 63;
        float lo = Wn[(2 * k2) * ED + c];
        float hi = Wn[(2 * k2 + 1) * ED + c];
        float* dst = sWp + k2 * WROW + woff(c);
        dst[0] = lo; dst[1] = hi;
    }

    const int cidx = t & 15, m = t >> 4;
    const int cg   = cidx * 4;
    const int wcol = woff(cg);
    const int swz  = (m >> 1) & 3;
    const int sub  = t & 7;
    const int el0  = t >> 3;
    const int el1  = 32 + el0;
    const int rs0  = (el0 >> 3) & 3, rs1 = (el1 >> 3) & 3;
    const int c0s  = sub >> 1, c1s = 4 + (sub >> 1), osub = 4 * (sub & 1);
    float4 bn4 = *(const float4*)(bn + cg);

    int tiles = (N + 63) >> 6;
    int step  = gridDim.x;
    int Nc    = N - 1;                          // clamp limit

    float4 st[4];
    auto load_rows = [&](int nb) {
        // clamped, unconditional loads (branch-free, front-batched)
        int g0 = imin(nb + el0, Nc), g1 = imin(nb + el1, Nc);
        const float4* rp0 = (const float4*)(nf + (size_t)g0 * ND);
        const float4* rp1 = (const float4*)(nf + (size_t)g1 * ND);
        st[0] = rp0[sub]; st[1] = rp0[sub + 8];
        st[2] = rp1[sub]; st[3] = rp1[sub + 8];
    };
    auto store_rows = [&](float* buf) {
        *(float4*)(buf + el0 * SJ + ((c0s ^ rs0) << 3) + osub) = st[0];
        *(float4*)(buf + el0 * SJ + ((c1s ^ rs0) << 3) + osub) = st[1];
        *(float4*)(buf + el1 * SJ + ((c0s ^ rs1) << 3) + osub) = st[2];
        *(float4*)(buf + el1 * SJ + ((c1s ^ rs1) << 3) + osub) = st[3];
    };

    if ((int)blockIdx.x < tiles) {
        load_rows((int)blockIdx.x << 6);
        store_rows(sA);
    }
    __syncthreads();

    int p = 0;
    for (int tile = blockIdx.x; tile < tiles; tile += step) {
        int base = tile << 6;
        load_rows(imin(tile + step, tiles - 1) << 6);   // prefetch (clamped)

        unsigned long long acc[4][4] = {};
        const float* aB = sA + p * ABUF + (m * 4) * SJ;
        #pragma unroll
        for (int c = 0; c < 8; c++) {
            int pc = (c ^ swz) << 3;
            #pragma unroll
            for (int half = 0; half < 2; half++) {
                int k2b = c * 4 + half * 2;
                ulonglong2 a0 = *(const ulonglong2*)(aB + 0 * SJ + pc + half * 4);
                ulonglong2 a1 = *(const ulonglong2*)(aB + 1 * SJ + pc + half * 4);
                ulonglong2 a2 = *(const ulonglong2*)(aB + 2 * SJ + pc + half * 4);
                ulonglong2 a3 = *(const ulonglong2*)(aB + 3 * SJ + pc + half * 4);
                const float* w0 = sWp + k2b * WROW + wcol;
                const float* w1 = w0 + WROW;
                ulonglong2 w0a = *(const ulonglong2*)(w0);
                ulonglong2 w0b = *(const ulonglong2*)(w0 + 4);
                ulonglong2 w1a = *(const ulonglong2*)(w1);
                ulonglong2 w1b = *(const ulonglong2*)(w1 + 4);
                fma_kpair(acc[0], a0, w0a, w0b, w1a, w1b);
                fma_kpair(acc[1], a1, w0a, w0b, w1a, w1b);
                fma_kpair(acc[2], a2, w0a, w0b, w1a, w1b);
                fma_kpair(acc[3], a3, w0a, w0b, w1a, w1b);
            }
        }

        #pragma unroll
        for (int i = 0; i < 4; i++) {
            int gn = base + m * 4 + i;
            if (gn >= N) continue;
            float l0, h0, l1, h1, l2, h2, l3, h3;
            unpack2(acc[i][0], l0, h0);
            unpack2(acc[i][1], l1, h1);
            unpack2(acc[i][2], l2, h2);
            unpack2(acc[i][3], l3, h3);
            float4 o = { l0 + h0 + bn4.x, l1 + h1 + bn4.y,
                         l2 + h2 + bn4.z, l3 + h3 + bn4.w };
            *(float4*)(g_nproj + (size_t)gn * ED + cg) = o;
        }

        store_rows(sA + (p ^ 1) * ABUF);
        __syncthreads();
        p ^= 1;
    }
}

// ---------------------------------------------------------------------------
// Kernel 2: main fused edge kernel (double-buffered, 1 sync/tile)
// ---------------------------------------------------------------------------
__global__ void __launch_bounds__(256, 2)
edge_kernel(const int* __restrict__ eidx,
            const float* __restrict__ egeo,
            const int* __restrict__ ebid,
            float* __restrict__ out,
            int E) {
    extern __shared__ __align__(16) char smem_raw[];
    float* sWp = (float*)smem_raw;             // [36][WROW]
    float* sA  = sWp + 36 * WROW;              // [2][64][SJ]
    int*  sBid = (int*)(sA + 2 * ABUF);        // [2][64]

    int t = threadIdx.x;
    for (int i = t; i < 36 * 64; i += 256) {
        int k2 = i >> 6, c = i & 63;
        float lo = g_wfold[(2 * k2) * ED + c];
        float hi = g_wfold[(2 * k2 + 1) * ED + c];
        float* dst = sWp + k2 * WROW + woff(c);
        dst[0] = lo; dst[1] = hi;
    }

    const int cidx = t & 15, m = t >> 4;
    const int cg   = cidx * 4;
    const int wcol = woff(cg);
    const int swz  = (m >> 1) & 3;
    const int sub  = t & 7;
    const int el0  = t >> 3;
    const int el1  = 32 + el0;
    const int rs0  = (el0 >> 3) & 3, rs1 = (el1 >> 3) & 3;
    const int c0s  = sub >> 1, c1s = 4 + (sub >> 1), osub = 4 * (sub & 1);
    const int elg  = t >> 1, hg = t & 1, rsg = (elg >> 3) & 3;
    float4 bgx4 = *(const float4*)(g_bgx + cg);

    int tiles = (E + 63) >> 6;
    int step  = gridDim.x;
    int Ec    = E - 1;

    float4 st[8];
    float4 geoS;
    int ns0, nd0, ns1, nd1;
    int bidS = 0, nbid = 0;

    auto load_idx = [&](int nb) {
        // clamped, unconditional
        int h0 = imin(nb + el0, Ec), h1 = imin(nb + el1, Ec);
        ns0 = eidx[h0];
        nd0 = eidx[E + h0];
        ns1 = eidx[h1];
        nd1 = eidx[E + h1];
        if (t < 64) nbid = ebid[imin(nb + t, Ec)];
    };
    auto load_rows = [&](int nb) {
        const float4* p4;
        p4 = (const float4*)(g_nproj + (size_t)ns0 * ED); st[0] = p4[sub]; st[1] = p4[sub + 8];
        p4 = (const float4*)(g_nproj + (size_t)nd0 * ED); st[2] = p4[sub]; st[3] = p4[sub + 8];
        p4 = (const float4*)(g_nproj + (size_t)ns1 * ED); st[4] = p4[sub]; st[5] = p4[sub + 8];
        p4 = (const float4*)(g_nproj + (size_t)nd1 * ED); st[6] = p4[sub]; st[7] = p4[sub + 8];
        if (t < 128) {
            int ge = imin(nb + elg, Ec);
            geoS = *(const float4*)(egeo + (size_t)ge * GD + 4 * hg);
        }
        bidS = nbid;
    };
    auto store_tile = [&](float* buf, int* bbid) {
        float4 p00 = mulc(st[0], st[2]), p01 = mulc(st[1], st[3]);
        float4 p10 = mulc(st[4], st[6]), p11 = mulc(st[5], st[7]);
        *(float4*)(buf + el0 * SJ + ((c0s ^ rs0) << 3) + osub) = p00;
        *(float4*)(buf + el0 * SJ + ((c1s ^ rs0) << 3) + osub) = p01;
        *(float4*)(buf + el1 * SJ + ((c0s ^ rs1) << 3) + osub) = p10;
        *(float4*)(buf + el1 * SJ + ((c1s ^ rs1) << 3) + osub) = p11;
        if (t < 128)
            *(float4*)(buf + elg * SJ + ((8 ^ rsg) << 3) + 4 * hg) = geoS;
        if (t < 64) bbid[t] = bidS;
    };

    {   // prologue: tile0 rows into buf0; idx for tile1 staged
        int nb0 = imin((int)blockIdx.x, tiles - 1) << 6;
        load_idx(nb0);
        load_rows(nb0);
        store_tile(sA, sBid);
        load_idx(imin((int)blockIdx.x + step, tiles - 1) << 6);
    }
    __syncthreads();

    int p = 0;
    for (int tile = blockIdx.x; tile < tiles; tile += step) {
        int base = tile << 6;
        load_rows(imin(tile + step, tiles - 1) << 6);
        load_idx(imin(tile + 2 * step, tiles - 1) << 6);

        unsigned long long acc[4][4] = {};
        const float* aB = sA + p * ABUF + (m * 4) * SJ;
        #pragma unroll
        for (int c = 0; c < 9; c++) {
            int pc = (c ^ swz) << 3;
            #pragma unroll
            for (int half = 0; half < 2; half++) {
                int k2b = c * 4 + half * 2;
                ulonglong2 a0 = *(const ulonglong2*)(aB + 0 * SJ + pc + half * 4);
                ulonglong2 a1 = *(const ulonglong2*)(aB + 1 * SJ + pc + half * 4);
                ulonglong2 a2 = *(const ulonglong2*)(aB + 2 * SJ + pc + half * 4);
                ulonglong2 a3 = *(const ulonglong2*)(aB + 3 * SJ + pc + half * 4);
                const float* w0 = sWp + k2b * WROW + wcol;
                const float* w1 = w0 + WROW;
                ulonglong2 w0a = *(const ulonglong2*)(w0);
                ulonglong2 w0b = *(const ulonglong2*)(w0 + 4);
                ulonglong2 w1a = *(const ulonglong2*)(w1);
                ulonglong2 w1b = *(const ulonglong2*)(w1 + 4);
                fma_kpair(acc[0], a0, w0a, w0b, w1a, w1b);
                fma_kpair(acc[1], a1, w0a, w0b, w1a, w1b);
                fma_kpair(acc[2], a2, w0a, w0b, w1a, w1b);
                fma_kpair(acc[3], a3, w0a, w0b, w1a, w1b);
            }
        }

        const int* bb = sBid + p * 64;
        #pragma unroll
        for (int i = 0; i < 4; i++) {
            int e  = m * 4 + i;
            int ge = base + e;
            if (ge >= E) continue;
            int bid = bb[e];
            const float* gb = g_gb + bid * (2 * ED);
            float4 gm = *(const float4*)(gb + cg);
            float4 bt = *(const float4*)(gb + ED + cg);
            float l0, h0, l1, h1, l2, h2, l3, h3;
            unpack2(acc[i][0], l0, h0);
            unpack2(acc[i][1], l1, h1);
            unpack2(acc[i][2], l2, h2);
            unpack2(acc[i][3], l3, h3);
            float x0 = l0 + h0 + bgx4.x;
            float x1 = l1 + h1 + bgx4.y;
            float x2 = l2 + h2 + bgx4.z;
            float x3 = l3 + h3 + bgx4.w;
            float4 o;
            o.x = fmaxf(fmaf(x0, gm.x, bt.x), 0.0f);
            o.y = fmaxf(fmaf(x1, gm.y, bt.y), 0.0f);
            o.z = fmaxf(fmaf(x2, gm.z, bt.z), 0.0f);
            o.w = fmaxf(fmaf(x3, gm.w, bt.w), 0.0f);
            *(float4*)(out + (size_t)ge * ED + cg) = o;
        }

        store_tile(sA + (p ^ 1) * ABUF, sBid + (p ^ 1) * 64);
        __syncthreads();
        p ^= 1;
    }
}

// ---------------- Launch ---------------------------------------------------
extern "C" void kernel_launch(void* const* d_in, const int* in_sizes, int n_in,
                              void* d_out, int out_size) {
    const float* nf   = (const float*)d_in[0];
    const int*   eidx = (const int*)d_in[1];
    const float* egeo = (const float*)d_in[2];
    const float* cond = (const float*)d_in[3];
    const int*   ebid = (const int*)d_in[4];
    const float* Wn   = (const float*)d_in[5];
    const float* bn   = (const float*)d_in[6];
    const float* Wg   = (const float*)d_in[7];
    const float* bg   = (const float*)d_in[8];
    const float* Wc   = (const float*)d_in[9];
    const float* bc   = (const float*)d_in[10];
    const float* Wx   = (const float*)d_in[11];

    int N = in_sizes[0] / ND;
    int E = in_sizes[2] / GD;
    int B = in_sizes[3] / CD;

    int smem_np = (32 * WROW + 2 * ABUF) * 4;              // 69632 B
    int smem_eg = (36 * WROW + 2 * ABUF) * 4 + 2 * 64 * 4; // 72448 B
    cudaFuncSetAttribute(setup_nproj_kernel, cudaFuncAttributeMaxDynamicSharedMemorySize, smem_np);
    cudaFuncSetAttribute(edge_kernel,        cudaFuncAttributeMaxDynamicSharedMemorySize, smem_eg);

    int grid = 296;   // 2 blocks/SM on 148 SMs
    setup_nproj_kernel<<<grid, 256, smem_np>>>(nf, Wn, bn, N, Wx, Wg, bg, cond, Wc, bc, B);

    int etiles = (E + 63) >> 6;
    int egrid  = etiles < grid ? etiles : grid;
    edge_kernel<<<egrid, 256, smem_eg>>>(eidx, egeo, ebid, (float*)d_out, E);
}

// round 12
// speedup vs baseline: 2.1766x; 1.4792x over previous
#include <cuda_runtime.h>
#include <cuda_fp16.h>

#define ND 64
#define ED 64
#define GD 8
#define GO 32
#define CD 512
#define KJ 72          // folded join K = ED + GD
#define KP 80          // padded K for fp16 mma (multiple of 16)
#define MAXN 100000
#define MAXB 64

// fp32 nproj GEMM
#define SJ   100
#define WROW 144
#define ABUF (64 * SJ)

// fp16 edge GEMM
#define SAH   88           // A smem row stride in halves (ldmatrix conflict-free)
#define ABUFH (64 * SAH)   // one A buffer in halves
#define SOUT  68           // sOut row stride in floats

__device__ float g_nproj[MAXN * ED];
__device__ float g_gb[MAXB * 2 * ED];
__device__ float g_wfold[KJ * ED];
__device__ float g_bgx[ED];
__device__ __align__(16) __half g_wfoldh[64 * KP];   // [n][k] fp16, k>=72 zero

// ---------------- helpers --------------------------------------------------
static __device__ __forceinline__ void fma2(unsigned long long& d,
                                            unsigned long long a,
                                            unsigned long long b) {
    asm("fma.rn.f32x2 %0, %1, %2, %0;" : "+l"(d) : "l"(a), "l"(b));
}
static __device__ __forceinline__ void unpack2(unsigned long long v, float& lo, float& hi) {
    asm("mov.b64 {%0, %1}, %2;" : "=f"(lo), "=f"(hi) : "l"(v));
}
static __device__ __forceinline__ int woff(int v) { return v * 2 + ((v >> 4) << 2); }
static __device__ __forceinline__ int imin(int a, int b) { return a < b ? a : b; }

static __device__ __forceinline__ void fma_kpair(unsigned long long* acc4,
                                                 ulonglong2 a,
                                                 ulonglong2 w0a, ulonglong2 w0b,
                                                 ulonglong2 w1a, ulonglong2 w1b) {
    fma2(acc4[0], a.x, w0a.x); fma2(acc4[1], a.x, w0a.y);
    fma2(acc4[2], a.x, w0b.x); fma2(acc4[3], a.x, w0b.y);
    fma2(acc4[0], a.y, w1a.x); fma2(acc4[1], a.y, w1a.y);
    fma2(acc4[2], a.y, w1b.x); fma2(acc4[3], a.y, w1b.y);
}
static __device__ __forceinline__ float4 mulc(float4 a, float4 b) {
    return make_float4(a.x * b.x, a.y * b.y, a.z * b.z, a.w * b.w);
}
static __device__ __forceinline__ unsigned pack_h2(float x, float y) {
    __half2 h = __floats2half2_rn(x, y);
    return *(unsigned*)&h;
}
static __device__ __forceinline__ void ldsm4(unsigned* r, unsigned addr) {
    asm volatile("ldmatrix.sync.aligned.m8n8.x4.shared.b16 {%0,%1,%2,%3}, [%4];"
                 : "=r"(r[0]), "=r"(r[1]), "=r"(r[2]), "=r"(r[3]) : "r"(addr));
}
static __device__ __forceinline__ void mma16816(float* d,
                                                unsigned a0, unsigned a1, unsigned a2, unsigned a3,
                                                unsigned b0, unsigned b1) {
    asm volatile("mma.sync.aligned.m16n8k16.row.col.f32.f16.f16.f32 "
                 "{%0,%1,%2,%3}, {%4,%5,%6,%7}, {%8,%9}, {%0,%1,%2,%3};"
                 : "+f"(d[0]), "+f"(d[1]), "+f"(d[2]), "+f"(d[3])
                 : "r"(a0), "r"(a1), "r"(a2), "r"(a3), "r"(b0), "r"(b1));
}

// ---------------------------------------------------------------------------
// Kernel 1: setup (film blocks 0..B-1, prep block B) + pipelined n_proj (all)
// ---------------------------------------------------------------------------
__global__ void __launch_bounds__(256, 2)
setup_nproj_kernel(const float* __restrict__ nf,
                   const float* __restrict__ Wn,
                   const float* __restrict__ bn,
                   int N,
                   const float* __restrict__ Wx,
                   const float* __restrict__ Wg,
                   const float* __restrict__ bg,
                   const float* __restrict__ cond,
                   const float* __restrict__ Wc,
                   const float* __restrict__ bc,
                   int B) {
    extern __shared__ __align__(16) char smem_raw[];
    int t = threadIdx.x;

    if ((int)blockIdx.x < B) {
        float* sc  = (float*)smem_raw;
        float* red = sc + CD;
        int b = blockIdx.x;
        for (int i = t; i < CD; i += 256) sc[i] = cond[b * CD + i];
        __syncthreads();
        int j  = t & 127;
        int kb = (t >> 7) * 256;
        float a0 = 0, a1 = 0, a2 = 0, a3 = 0;
        #pragma unroll 4
        for (int k = 0; k < 256; k += 4) {
            a0 = fmaf(sc[kb + k + 0], Wc[(kb + k + 0) * (2 * ED) + j], a0);
            a1 = fmaf(sc[kb + k + 1], Wc[(kb + k + 1) * (2 * ED) + j], a1);
            a2 = fmaf(sc[kb + k + 2], Wc[(kb + k + 2) * (2 * ED) + j], a2);
            a3 = fmaf(sc[kb + k + 3], Wc[(kb + k + 3) * (2 * ED) + j], a3);
        }
        red[t] = (a0 + a1) + (a2 + a3);
        __syncthreads();
        if (t < 128) {
            float acc = red[t] + red[t + 128] + bc[j];
            if (j < ED) acc += 1.0f;
            g_gb[b * (2 * ED) + j] = acc;
        }
    } else if ((int)blockIdx.x == B) {
        for (int idx = t; idx < KJ * ED; idx += 256) {
            int k = idx >> 6, j = idx & 63;
            float v;
            if (k < ED) {
                v = Wx[k * ED + j];
            } else {
                int g = k - ED;
                v = 0.0f;
                #pragma unroll 8
                for (int m = 0; m < GO; m++)
                    v = fmaf(Wg[g * GO + m], Wx[(ED + m) * ED + j], v);
            }
            g_wfold[idx] = v;
        }
        for (int j = t; j < ED; j += 256) {
            float v = 0.0f;
            #pragma unroll 8
            for (int m = 0; m < GO; m++)
                v = fmaf(bg[m], Wx[(ED + m) * ED + j], v);
            g_bgx[j] = v;
        }
        __syncthreads();
        // fp16 transposed padded copy for the edge kernel's tensor-core GEMM
        for (int i = t; i < 64 * KP; i += 256) {
            int n = i / KP, k = i - n * KP;
            float v = (k < KJ) ? g_wfold[k * ED + n] : 0.0f;
            g_wfoldh[n * KP + k] = __float2half_rn(v);
        }
    }
    __syncthreads();   // smem reuse barrier

    // ---- n_proj phase (fp32 f32x2, double-buffered) ----
    float* sWp = (float*)smem_raw;             // [32][WROW]
    float* sA  = sWp + 32 * WROW;              // [2][64][SJ]

    for (int i = t; i < 32 * 64; i += 256) {
        int k2 = i >> 6, c = i & 63;
        float lo = Wn[(2 * k2) * ED + c];
        float hi = Wn[(2 * k2 + 1) * ED + c];
        float* dst = sWp + k2 * WROW + woff(c);
        dst[0] = lo; dst[1] = hi;
    }

    const int cidx = t & 15, m = t >> 4;
    const int cg   = cidx * 4;
    const int wcol = woff(cg);
    const int swz  = (m >> 1) & 3;
    const int sub  = t & 7;
    const int el0  = t >> 3;
    const int el1  = 32 + el0;
    const int rs0  = (el0 >> 3) & 3, rs1 = (el1 >> 3) & 3;
    const int c0s  = sub >> 1, c1s = 4 + (sub >> 1), osub = 4 * (sub & 1);
    float4 bn4 = *(const float4*)(bn + cg);

    int tiles = (N + 63) >> 6;
    int step  = gridDim.x;
    int Nc    = N - 1;

    float4 st[4];
    auto load_rows = [&](int nb) {
        int g0 = imin(nb + el0, Nc), g1 = imin(nb + el1, Nc);
        const float4* rp0 = (const float4*)(nf + (size_t)g0 * ND);
        const float4* rp1 = (const float4*)(nf + (size_t)g1 * ND);
        st[0] = rp0[sub]; st[1] = rp0[sub + 8];
        st[2] = rp1[sub]; st[3] = rp1[sub + 8];
    };
    auto store_rows = [&](float* buf) {
        *(float4*)(buf + el0 * SJ + ((c0s ^ rs0) << 3) + osub) = st[0];
        *(float4*)(buf + el0 * SJ + ((c1s ^ rs0) << 3) + osub) = st[1];
        *(float4*)(buf + el1 * SJ + ((c0s ^ rs1) << 3) + osub) = st[2];
        *(float4*)(buf + el1 * SJ + ((c1s ^ rs1) << 3) + osub) = st[3];
    };

    if ((int)blockIdx.x < tiles) {
        load_rows((int)blockIdx.x << 6);
        store_rows(sA);
    }
    __syncthreads();

    int p = 0;
    for (int tile = blockIdx.x; tile < tiles; tile += step) {
        int base = tile << 6;
        load_rows(imin(tile + step, tiles - 1) << 6);

        unsigned long long acc[4][4] = {};
        const float* aB = sA + p * ABUF + (m * 4) * SJ;
        #pragma unroll
        for (int c = 0; c < 8; c++) {
            int pc = (c ^ swz) << 3;
            #pragma unroll
            for (int half = 0; half < 2; half++) {
                int k2b = c * 4 + half * 2;
                ulonglong2 a0 = *(const ulonglong2*)(aB + 0 * SJ + pc + half * 4);
                ulonglong2 a1 = *(const ulonglong2*)(aB + 1 * SJ + pc + half * 4);
                ulonglong2 a2 = *(const ulonglong2*)(aB + 2 * SJ + pc + half * 4);
                ulonglong2 a3 = *(const ulonglong2*)(aB + 3 * SJ + pc + half * 4);
                const float* w0 = sWp + k2b * WROW + wcol;
                const float* w1 = w0 + WROW;
                ulonglong2 w0a = *(const ulonglong2*)(w0);
                ulonglong2 w0b = *(const ulonglong2*)(w0 + 4);
                ulonglong2 w1a = *(const ulonglong2*)(w1);
                ulonglong2 w1b = *(const ulonglong2*)(w1 + 4);
                fma_kpair(acc[0], a0, w0a, w0b, w1a, w1b);
                fma_kpair(acc[1], a1, w0a, w0b, w1a, w1b);
                fma_kpair(acc[2], a2, w0a, w0b, w1a, w1b);
                fma_kpair(acc[3], a3, w0a, w0b, w1a, w1b);
            }
        }

        #pragma unroll
        for (int i = 0; i < 4; i++) {
            int gn = base + m * 4 + i;
            if (gn >= N) continue;
            float l0, h0, l1, h1, l2, h2, l3, h3;
            unpack2(acc[i][0], l0, h0);
            unpack2(acc[i][1], l1, h1);
            unpack2(acc[i][2], l2, h2);
            unpack2(acc[i][3], l3, h3);
            float4 o = { l0 + h0 + bn4.x, l1 + h1 + bn4.y,
                         l2 + h2 + bn4.z, l3 + h3 + bn4.w };
            *(float4*)(g_nproj + (size_t)gn * ED + cg) = o;
        }

        store_rows(sA + (p ^ 1) * ABUF);
        __syncthreads();
        p ^= 1;
    }
}

// ---------------------------------------------------------------------------
// Kernel 2: fused edge kernel — fp16 tensor-core GEMM, fp32 accumulate
// Tile 64 edges x 64 cols x K80. 8 warps: each m16 x n32, 20 HMMA/tile.
// ---------------------------------------------------------------------------
__global__ void __launch_bounds__(256, 2)
edge_kernel(const int* __restrict__ eidx,
            const float* __restrict__ egeo,
            const int* __restrict__ ebid,
            float* __restrict__ out,
            int E) {
    extern __shared__ __align__(16) char smem_raw[];
    __half* sWh  = (__half*)smem_raw;            // [64 n][SAH]
    __half* sAh  = sWh + 64 * SAH;               // [2][64 edge][SAH]
    float*  sOut = (float*)(sAh + 2 * ABUFH);    // [64][SOUT]
    int*    sBid = (int*)(sOut + 64 * SOUT);     // [2][64]

    int t = threadIdx.x;

    // zero A buffers once (pad seg must not contain NaN/Inf bit garbage)
    for (int i = t; i < 2 * ABUFH / 8; i += 256)
        ((uint4*)sAh)[i] = make_uint4(0, 0, 0, 0);
    // stage W fp16 [n][k] with pad zeros
    for (int i = t; i < 64 * (KP / 8); i += 256) {
        int n = i / 10, seg = i - n * 10;
        uint4 v = *(const uint4*)(g_wfoldh + n * KP + seg * 8);
        *(uint4*)(sWh + n * SAH + seg * 8) = v;
    }

    const int w = t >> 5, l = t & 31;
    const int m0  = (w & 3) * 16;
    const int nbw = (w >> 2) * 32;
    const int sub = t & 7;
    const int el0 = t >> 3;
    const int el1 = 32 + el0;
    const int elg = t >> 1, hg = t & 1;          // geo task (t<128)

    unsigned sWh_s = (unsigned)__cvta_generic_to_shared(sWh);
    unsigned sAh_s = (unsigned)__cvta_generic_to_shared(sAh);
    const unsigned aOff  = ((m0 + (l & 15)) * SAH + ((l >> 4) << 3)) * 2;
    const unsigned bOff0 = ((nbw + (((l >> 3) & 1) << 3) + (l & 7)) * SAH + ((l >> 4) << 3)) * 2;
    const unsigned bOff1 = bOff0 + 16 * SAH * 2;

    float4 bgxa = *(const float4*)(g_bgx + sub * 8);
    float4 bgxb = *(const float4*)(g_bgx + sub * 8 + 4);

    int tiles = (E + 63) >> 6;
    int step  = gridDim.x;
    int Ec    = E - 1;

    float4 st[8];
    float4 geoS;
    int ns0, nd0, ns1, nd1;
    int bidS = 0, nbid = 0;

    auto load_idx = [&](int nb) {
        int h0 = imin(nb + el0, Ec), h1 = imin(nb + el1, Ec);
        ns0 = eidx[h0];
        nd0 = eidx[E + h0];
        ns1 = eidx[h1];
        nd1 = eidx[E + h1];
        if (t < 64) nbid = ebid[imin(nb + t, Ec)];
    };
    auto load_rows = [&](int nb) {
        const float4* p4;
        p4 = (const float4*)(g_nproj + (size_t)ns0 * ED);
        st[0] = p4[2 * sub]; st[1] = p4[2 * sub + 1];
        p4 = (const float4*)(g_nproj + (size_t)nd0 * ED);
        st[2] = p4[2 * sub]; st[3] = p4[2 * sub + 1];
        p4 = (const float4*)(g_nproj + (size_t)ns1 * ED);
        st[4] = p4[2 * sub]; st[5] = p4[2 * sub + 1];
        p4 = (const float4*)(g_nproj + (size_t)nd1 * ED);
        st[6] = p4[2 * sub]; st[7] = p4[2 * sub + 1];
        if (t < 128) {
            int ge = imin(nb + elg, Ec);
            geoS = *(const float4*)(egeo + (size_t)ge * GD + 4 * hg);
        }
        bidS = nbid;
    };
    auto store_tile = [&](__half* buf, int* bbid) {
        float4 p00 = mulc(st[0], st[2]), p01 = mulc(st[1], st[3]);
        float4 p10 = mulc(st[4], st[6]), p11 = mulc(st[5], st[7]);
        uint4 u0, u1;
        u0.x = pack_h2(p00.x, p00.y); u0.y = pack_h2(p00.z, p00.w);
        u0.z = pack_h2(p01.x, p01.y); u0.w = pack_h2(p01.z, p01.w);
        u1.x = pack_h2(p10.x, p10.y); u1.y = pack_h2(p10.z, p10.w);
        u1.z = pack_h2(p11.x, p11.y); u1.w = pack_h2(p11.z, p11.w);
        *(uint4*)(buf + el0 * SAH + sub * 8) = u0;
        *(uint4*)(buf + el1 * SAH + sub * 8) = u1;
        if (t < 128) {
            uint2 g2;
            g2.x = pack_h2(geoS.x, geoS.y);
            g2.y = pack_h2(geoS.z, geoS.w);
            *(uint2*)(buf + elg * SAH + 64 + 4 * hg) = g2;
        }
        if (t < 64) bbid[t] = bidS;
    };

    {   // prologue
        int nb0 = imin((int)blockIdx.x, tiles - 1) << 6;
        load_idx(nb0);
        load_rows(nb0);
        // barrier: the one-time zeroing of sAh (all threads, strided) must
        // complete before any thread stores tile-0 data into sAh[0]
        __syncthreads();
        store_tile(sAh, sBid);
        load_idx(imin((int)blockIdx.x + step, tiles - 1) << 6);
    }
    __syncthreads();

    int p = 0;
    for (int tile = blockIdx.x; tile < tiles; tile += step) {
        int base = tile << 6;
        load_rows(imin(tile + step, tiles - 1) << 6);
        load_idx(imin(tile + 2 * step, tiles - 1) << 6);

        // ---- tensor-core GEMM on buf p ----
        float d[4][4] = {};
        unsigned aT = sAh_s + (p ? ABUFH * 2 : 0);
        #pragma unroll
        for (int ks = 0; ks < 5; ks++) {
            unsigned ar[4], b0[4], b1[4];
            ldsm4(ar, aT + aOff + ks * 32);
            ldsm4(b0, sWh_s + bOff0 + ks * 32);
            ldsm4(b1, sWh_s + bOff1 + ks * 32);
            mma16816(d[0], ar[0], ar[1], ar[2], ar[3], b0[0], b0[2]);
            mma16816(d[1], ar[0], ar[1], ar[2], ar[3], b0[1], b0[3]);
            mma16816(d[2], ar[0], ar[1], ar[2], ar[3], b1[0], b1[2]);
            mma16816(d[3], ar[0], ar[1], ar[2], ar[3], b1[1], b1[3]);
        }

        __syncthreads();   // prior epilogue readers done; sOut free; mma readers done

        // ---- fragment store -> sOut; stage next tile -> sA[p^1] ----
        {
            int fr = m0 + (l >> 2);
            int fc = nbw + 2 * (l & 3);
            #pragma unroll
            for (int nt = 0; nt < 4; nt++) {
                *(float2*)(sOut + fr * SOUT + fc + nt * 8)       = make_float2(d[nt][0], d[nt][1]);
                *(float2*)(sOut + (fr + 8) * SOUT + fc + nt * 8) = make_float2(d[nt][2], d[nt][3]);
            }
        }
        store_tile(sAh + (p ^ 1) * ABUFH, sBid + (p ^ 1) * 64);
        __syncthreads();   // sOut ready; sA[p^1] ready

        // ---- epilogue: FiLM + relu, coalesced stores ----
        const int* bb = sBid + p * 64;
        #pragma unroll
        for (int half = 0; half < 2; half++) {
            int e  = half ? el1 : el0;
            int ge = base + e;
            if (ge >= E) continue;
            int bid = bb[e];
            const float* gb = g_gb + bid * (2 * ED);
            float4 gma = *(const float4*)(gb + sub * 8);
            float4 gmb = *(const float4*)(gb + sub * 8 + 4);
            float4 bta = *(const float4*)(gb + ED + sub * 8);
            float4 btb = *(const float4*)(gb + ED + sub * 8 + 4);
            float4 xa = *(float4*)(sOut + e * SOUT + sub * 8);
            float4 xb = *(float4*)(sOut + e * SOUT + sub * 8 + 4);
            float4 oa, ob;
            oa.x = fmaxf(fmaf(xa.x + bgxa.x, gma.x, bta.x), 0.0f);
            oa.y = fmaxf(fmaf(xa.y + bgxa.y, gma.y, bta.y), 0.0f);
            oa.z = fmaxf(fmaf(xa.z + bgxa.z, gma.z, bta.z), 0.0f);
            oa.w = fmaxf(fmaf(xa.w + bgxa.w, gma.w, bta.w), 0.0f);
            ob.x = fmaxf(fmaf(xb.x + bgxb.x, gmb.x, btb.x), 0.0f);
            ob.y = fmaxf(fmaf(xb.y + bgxb.y, gmb.y, btb.y), 0.0f);
            ob.z = fmaxf(fmaf(xb.z + bgxb.z, gmb.z, btb.z), 0.0f);
            ob.w = fmaxf(fmaf(xb.w + bgxb.w, gmb.w, btb.w), 0.0f);
            float4* op = (float4*)(out + (size_t)ge * ED + sub * 8);
            op[0] = oa; op[1] = ob;
        }
        p ^= 1;
    }
}

// ---------------- Launch ---------------------------------------------------
extern "C" void kernel_launch(void* const* d_in, const int* in_sizes, int n_in,
                              void* d_out, int out_size) {
    const float* nf   = (const float*)d_in[0];
    const int*   eidx = (const int*)d_in[1];
    const float* egeo = (const float*)d_in[2];
    const float* cond = (const float*)d_in[3];
    const int*   ebid = (const int*)d_in[4];
    const float* Wn   = (const float*)d_in[5];
    const float* bn   = (const float*)d_in[6];
    const float* Wg   = (const float*)d_in[7];
    const float* bg   = (const float*)d_in[8];
    const float* Wc   = (const float*)d_in[9];
    const float* bc   = (const float*)d_in[10];
    const float* Wx   = (const float*)d_in[11];

    int N = in_sizes[0] / ND;
    int E = in_sizes[2] / GD;
    int B = in_sizes[3] / CD;

    int smem_np = (32 * WROW + 2 * ABUF) * 4;                         // 69632 B
    int smem_eg = (64 * SAH + 2 * ABUFH) * 2 + 64 * SOUT * 4 + 2 * 64 * 4;  // 51712 B
    cudaFuncSetAttribute(setup_nproj_kernel, cudaFuncAttributeMaxDynamicSharedMemorySize, smem_np);
    cudaFuncSetAttribute(edge_kernel,        cudaFuncAttributeMaxDynamicSharedMemorySize, smem_eg);

    int grid = 296;   // 2 blocks/SM on 148 SMs
    setup_nproj_kernel<<<grid, 256, smem_np>>>(nf, Wn, bn, N, Wx, Wg, bg, cond, Wc, bc, B);

    int etiles = (E + 63) >> 6;
    int egrid  = etiles < grid ? etiles : grid;
    edge_kernel<<<egrid, 256, smem_eg>>>(eidx, egeo, ebid, (float*)d_out, E);
}

// round 14
// speedup vs baseline: 2.4453x; 1.1235x over previous
#include <cuda_runtime.h>
#include <cuda_fp16.h>

#define ND 64
#define ED 64
#define GD 8
#define GO 32
#define CD 512
#define KJ 72          // folded join K = ED + GD
#define KP 80          // padded K for fp16 mma (multiple of 16)
#define MAXN 100000
#define MAXB 64

// fp32 nproj GEMM
#define SJ   100
#define WROW 144
#define ABUF (64 * SJ)

// fp16 edge GEMM
#define SAH   88           // A smem row stride in halves (ldmatrix conflict-free)
#define ABUFH (64 * SAH)   // one A buffer in halves
#define SOUT  68           // sOut row stride in floats

__device__ __align__(16) __half g_nproj[MAXN * ED];  // fp16: 12.8 MB, row = 128 B
__device__ float g_gb[MAXB * 2 * ED];
__device__ float g_wfold[KJ * ED];
__device__ float g_bgx[ED];
__device__ __align__(16) __half g_wfoldh[64 * KP];   // [n][k] fp16, k>=72 zero

// ---------------- helpers --------------------------------------------------
static __device__ __forceinline__ void fma2(unsigned long long& d,
                                            unsigned long long a,
                                            unsigned long long b) {
    asm("fma.rn.f32x2 %0, %1, %2, %0;" : "+l"(d) : "l"(a), "l"(b));
}
static __device__ __forceinline__ void unpack2(unsigned long long v, float& lo, float& hi) {
    asm("mov.b64 {%0, %1}, %2;" : "=f"(lo), "=f"(hi) : "l"(v));
}
static __device__ __forceinline__ int woff(int v) { return v * 2 + ((v >> 4) << 2); }
static __device__ __forceinline__ int imin(int a, int b) { return a < b ? a : b; }

static __device__ __forceinline__ void fma_kpair(unsigned long long* acc4,
                                                 ulonglong2 a,
                                                 ulonglong2 w0a, ulonglong2 w0b,
                                                 ulonglong2 w1a, ulonglong2 w1b) {
    fma2(acc4[0], a.x, w0a.x); fma2(acc4[1], a.x, w0a.y);
    fma2(acc4[2], a.x, w0b.x); fma2(acc4[3], a.x, w0b.y);
    fma2(acc4[0], a.y, w1a.x); fma2(acc4[1], a.y, w1a.y);
    fma2(acc4[2], a.y, w1b.x); fma2(acc4[3], a.y, w1b.y);
}
static __device__ __forceinline__ unsigned pack_h2(float x, float y) {
    __half2 h = __floats2half2_rn(x, y);
    return *(unsigned*)&h;
}
static __device__ __forceinline__ unsigned hmul2u(unsigned a, unsigned b) {
    __half2 r = __hmul2(*(__half2*)&a, *(__half2*)&b);
    return *(unsigned*)&r;
}
static __device__ __forceinline__ void ldsm4(unsigned* r, unsigned addr) {
    asm volatile("ldmatrix.sync.aligned.m8n8.x4.shared.b16 {%0,%1,%2,%3}, [%4];"
                 : "=r"(r[0]), "=r"(r[1]), "=r"(r[2]), "=r"(r[3]) : "r"(addr));
}
static __device__ __forceinline__ void mma16816(float* d,
                                                unsigned a0, unsigned a1, unsigned a2, unsigned a3,
                                                unsigned b0, unsigned b1) {
    asm volatile("mma.sync.aligned.m16n8k16.row.col.f32.f16.f16.f32 "
                 "{%0,%1,%2,%3}, {%4,%5,%6,%7}, {%8,%9}, {%0,%1,%2,%3};"
                 : "+f"(d[0]), "+f"(d[1]), "+f"(d[2]), "+f"(d[3])
                 : "r"(a0), "r"(a1), "r"(a2), "r"(a3), "r"(b0), "r"(b1));
}

// ---------------------------------------------------------------------------
// Kernel 1: setup (film blocks 0..B-1, prep block B) + pipelined n_proj (all)
// n_proj computed in fp32, stored as fp16.
// ---------------------------------------------------------------------------
__global__ void __launch_bounds__(256, 2)
setup_nproj_kernel(const float* __restrict__ nf,
                   const float* __restrict__ Wn,
                   const float* __restrict__ bn,
                   int N,
                   const float* __restrict__ Wx,
                   const float* __restrict__ Wg,
                   const float* __restrict__ bg,
                   const float* __restrict__ cond,
                   const float* __restrict__ Wc,
                   const float* __restrict__ bc,
                   int B) {
    extern __shared__ __align__(16) char smem_raw[];
    int t = threadIdx.x;

    if ((int)blockIdx.x < B) {
        float* sc  = (float*)smem_raw;
        float* red = sc + CD;
        int b = blockIdx.x;
        for (int i = t; i < CD; i += 256) sc[i] = cond[b * CD + i];
        __syncthreads();
        int j  = t & 127;
        int kb = (t >> 7) * 256;
        float a0 = 0, a1 = 0, a2 = 0, a3 = 0;
        #pragma unroll 4
        for (int k = 0; k < 256; k += 4) {
            a0 = fmaf(sc[kb + k + 0], Wc[(kb + k + 0) * (2 * ED) + j], a0);
            a1 = fmaf(sc[kb + k + 1], Wc[(kb + k + 1) * (2 * ED) + j], a1);
            a2 = fmaf(sc[kb + k + 2], Wc[(kb + k + 2) * (2 * ED) + j], a2);
            a3 = fmaf(sc[kb + k + 3], Wc[(kb + k + 3) * (2 * ED) + j], a3);
        }
        red[t] = (a0 + a1) + (a2 + a3);
        __syncthreads();
        if (t < 128) {
            float acc = red[t] + red[t + 128] + bc[j];
            if (j < ED) acc += 1.0f;
            g_gb[b * (2 * ED) + j] = acc;
        }
    } else if ((int)blockIdx.x == B) {
        for (int idx = t; idx < KJ * ED; idx += 256) {
            int k = idx >> 6, j = idx & 63;
            float v;
            if (k < ED) {
                v = Wx[k * ED + j];
            } else {
                int g = k - ED;
                v = 0.0f;
                #pragma unroll 8
                for (int m = 0; m < GO; m++)
                    v = fmaf(Wg[g * GO + m], Wx[(ED + m) * ED + j], v);
            }
            g_wfold[idx] = v;
        }
        for (int j = t; j < ED; j += 256) {
            float v = 0.0f;
            #pragma unroll 8
            for (int m = 0; m < GO; m++)
                v = fmaf(bg[m], Wx[(ED + m) * ED + j], v);
            g_bgx[j] = v;
        }
        __syncthreads();
        // fp16 transposed padded copy for the edge kernel's tensor-core GEMM
        for (int i = t; i < 64 * KP; i += 256) {
            int n = i / KP, k = i - n * KP;
            float v = (k < KJ) ? g_wfold[k * ED + n] : 0.0f;
            g_wfoldh[n * KP + k] = __float2half_rn(v);
        }
    }
    __syncthreads();   // smem reuse barrier

    // ---- n_proj phase (fp32 f32x2, double-buffered; fp16 output) ----
    float* sWp = (float*)smem_raw;             // [32][WROW]
    float* sA  = sWp + 32 * WROW;              // [2][64][SJ]

    for (int i = t; i < 32 * 64; i += 256) {
        int k2 = i >> 6, c = i & 63;
        float lo = Wn[(2 * k2) * ED + c];
        float hi = Wn[(2 * k2 + 1) * ED + c];
        float* dst = sWp + k2 * WROW + woff(c);
        dst[0] = lo; dst[1] = hi;
    }

    const int cidx = t & 15, m = t >> 4;
    const int cg   = cidx * 4;
    const int wcol = woff(cg);
    const int swz  = (m >> 1) & 3;
    const int sub  = t & 7;
    const int el0  = t >> 3;
    const int el1  = 32 + el0;
    const int rs0  = (el0 >> 3) & 3, rs1 = (el1 >> 3) & 3;
    const int c0s  = sub >> 1, c1s = 4 + (sub >> 1), osub = 4 * (sub & 1);
    float4 bn4 = *(const float4*)(bn + cg);

    int tiles = (N + 63) >> 6;
    int step  = gridDim.x;
    int Nc    = N - 1;

    float4 st[4];
    auto load_rows = [&](int nb) {
        int g0 = imin(nb + el0, Nc), g1 = imin(nb + el1, Nc);
        const float4* rp0 = (const float4*)(nf + (size_t)g0 * ND);
        const float4* rp1 = (const float4*)(nf + (size_t)g1 * ND);
        st[0] = rp0[sub]; st[1] = rp0[sub + 8];
        st[2] = rp1[sub]; st[3] = rp1[sub + 8];
    };
    auto store_rows = [&](float* buf) {
        *(float4*)(buf + el0 * SJ + ((c0s ^ rs0) << 3) + osub) = st[0];
        *(float4*)(buf + el0 * SJ + ((c1s ^ rs0) << 3) + osub) = st[1];
        *(float4*)(buf + el1 * SJ + ((c0s ^ rs1) << 3) + osub) = st[2];
        *(float4*)(buf + el1 * SJ + ((c1s ^ rs1) << 3) + osub) = st[3];
    };

    if ((int)blockIdx.x < tiles) {
        load_rows((int)blockIdx.x << 6);
        store_rows(sA);
    }
    __syncthreads();

    int p = 0;
    for (int tile = blockIdx.x; tile < tiles; tile += step) {
        int base = tile << 6;
        load_rows(imin(tile + step, tiles - 1) << 6);

        unsigned long long acc[4][4] = {};
        const float* aB = sA + p * ABUF + (m * 4) * SJ;
        #pragma unroll
        for (int c = 0; c < 8; c++) {
            int pc = (c ^ swz) << 3;
            #pragma unroll
            for (int half = 0; half < 2; half++) {
                int k2b = c * 4 + half * 2;
                ulonglong2 a0 = *(const ulonglong2*)(aB + 0 * SJ + pc + half * 4);
                ulonglong2 a1 = *(const ulonglong2*)(aB + 1 * SJ + pc + half * 4);
                ulonglong2 a2 = *(const ulonglong2*)(aB + 2 * SJ + pc + half * 4);
                ulonglong2 a3 = *(const ulonglong2*)(aB + 3 * SJ + pc + half * 4);
                const float* w0 = sWp + k2b * WROW + wcol;
                const float* w1 = w0 + WROW;
                ulonglong2 w0a = *(const ulonglong2*)(w0);
                ulonglong2 w0b = *(const ulonglong2*)(w0 + 4);
                ulonglong2 w1a = *(const ulonglong2*)(w1);
                ulonglong2 w1b = *(const ulonglong2*)(w1 + 4);
                fma_kpair(acc[0], a0, w0a, w0b, w1a, w1b);
                fma_kpair(acc[1], a1, w0a, w0b, w1a, w1b);
                fma_kpair(acc[2], a2, w0a, w0b, w1a, w1b);
                fma_kpair(acc[3], a3, w0a, w0b, w1a, w1b);
            }
        }

        #pragma unroll
        for (int i = 0; i < 4; i++) {
            int gn = base + m * 4 + i;
            if (gn >= N) continue;
            float l0, h0, l1, h1, l2, h2, l3, h3;
            unpack2(acc[i][0], l0, h0);
            unpack2(acc[i][1], l1, h1);
            unpack2(acc[i][2], l2, h2);
            unpack2(acc[i][3], l3, h3);
            uint2 u;
            u.x = pack_h2(l0 + h0 + bn4.x, l1 + h1 + bn4.y);
            u.y = pack_h2(l2 + h2 + bn4.z, l3 + h3 + bn4.w);
            *(uint2*)(g_nproj + (size_t)gn * ED + cg) = u;
        }

        store_rows(sA + (p ^ 1) * ABUF);
        __syncthreads();
        p ^= 1;
    }
}

// ---------------------------------------------------------------------------
// Kernel 2: fused edge kernel — fp16 gather + fp16 tensor-core GEMM
// Tile 64 edges x 64 cols x K80. 8 warps: each m16 x n32, 20 HMMA/tile.
// ---------------------------------------------------------------------------
__global__ void __launch_bounds__(256, 2)
edge_kernel(const int* __restrict__ eidx,
            const float* __restrict__ egeo,
            const int* __restrict__ ebid,
            float* __restrict__ out,
            int E) {
    extern __shared__ __align__(16) char smem_raw[];
    __half* sWh  = (__half*)smem_raw;            // [64 n][SAH]
    __half* sAh  = sWh + 64 * SAH;               // [2][64 edge][SAH]
    float*  sOut = (float*)(sAh + 2 * ABUFH);    // [64][SOUT]
    int*    sBid = (int*)(sOut + 64 * SOUT);     // [2][64]

    int t = threadIdx.x;

    // zero A buffers once (pad seg must not contain NaN/Inf bit garbage)
    for (int i = t; i < 2 * ABUFH / 8; i += 256)
        ((uint4*)sAh)[i] = make_uint4(0, 0, 0, 0);
    // stage W fp16 [n][k] with pad zeros
    for (int i = t; i < 64 * (KP / 8); i += 256) {
        int n = i / 10, seg = i - n * 10;
        uint4 v = *(const uint4*)(g_wfoldh + n * KP + seg * 8);
        *(uint4*)(sWh + n * SAH + seg * 8) = v;
    }

    const int w = t >> 5, l = t & 31;
    const int m0  = (w & 3) * 16;
    const int nbw = (w >> 2) * 32;
    const int sub = t & 7;
    const int el0 = t >> 3;
    const int el1 = 32 + el0;
    const int elg = t >> 1, hg = t & 1;          // geo task (t<128)

    unsigned sWh_s = (unsigned)__cvta_generic_to_shared(sWh);
    unsigned sAh_s = (unsigned)__cvta_generic_to_shared(sAh);
    const unsigned aOff  = ((m0 + (l & 15)) * SAH + ((l >> 4) << 3)) * 2;
    const unsigned bOff0 = ((nbw + (((l >> 3) & 1) << 3) + (l & 7)) * SAH + ((l >> 4) << 3)) * 2;
    const unsigned bOff1 = bOff0 + 16 * SAH * 2;

    float4 bgxa = *(const float4*)(g_bgx + sub * 8);
    float4 bgxb = *(const float4*)(g_bgx + sub * 8 + 4);

    int tiles = (E + 63) >> 6;
    int step  = gridDim.x;
    int Ec    = E - 1;

    uint4 su[4];                   // fp16 rows: src0, dst0, src1, dst1
    float4 geoS;
    int ns0, nd0, ns1, nd1;
    int bidS = 0, nbid = 0;

    auto load_idx = [&](int nb) {
        int h0 = imin(nb + el0, Ec), h1 = imin(nb + el1, Ec);
        ns0 = eidx[h0];
        nd0 = eidx[E + h0];
        ns1 = eidx[h1];
        nd1 = eidx[E + h1];
        if (t < 64) nbid = ebid[imin(nb + t, Ec)];
    };
    auto load_rows = [&](int nb) {
        // one contiguous uint4 per lane: 8 lanes cover the full 128 B row
        su[0] = ((const uint4*)(g_nproj + (size_t)ns0 * ED))[sub];
        su[1] = ((const uint4*)(g_nproj + (size_t)nd0 * ED))[sub];
        su[2] = ((const uint4*)(g_nproj + (size_t)ns1 * ED))[sub];
        su[3] = ((const uint4*)(g_nproj + (size_t)nd1 * ED))[sub];
        if (t < 128) {
            int ge = imin(nb + elg, Ec);
            geoS = *(const float4*)(egeo + (size_t)ge * GD + 4 * hg);
        }
        bidS = nbid;
    };
    auto store_tile = [&](__half* buf, int* bbid) {
        uint4 u0, u1;
        u0.x = hmul2u(su[0].x, su[1].x); u0.y = hmul2u(su[0].y, su[1].y);
        u0.z = hmul2u(su[0].z, su[1].z); u0.w = hmul2u(su[0].w, su[1].w);
        u1.x = hmul2u(su[2].x, su[3].x); u1.y = hmul2u(su[2].y, su[3].y);
        u1.z = hmul2u(su[2].z, su[3].z); u1.w = hmul2u(su[2].w, su[3].w);
        *(uint4*)(buf + el0 * SAH + sub * 8) = u0;
        *(uint4*)(buf + el1 * SAH + sub * 8) = u1;
        if (t < 128) {
            uint2 g2;
            g2.x = pack_h2(geoS.x, geoS.y);
            g2.y = pack_h2(geoS.z, geoS.w);
            *(uint2*)(buf + elg * SAH + 64 + 4 * hg) = g2;
        }
        if (t < 64) bbid[t] = bidS;
    };

    {   // prologue
        int nb0 = imin((int)blockIdx.x, tiles - 1) << 6;
        load_idx(nb0);
        load_rows(nb0);
        // barrier: one-time zeroing of sAh must complete before tile-0 staging
        __syncthreads();
        store_tile(sAh, sBid);
        load_idx(imin((int)blockIdx.x + step, tiles - 1) << 6);
    }
    __syncthreads();

    int p = 0;
    for (int tile = blockIdx.x; tile < tiles; tile += step) {
        int base = tile << 6;
        load_rows(imin(tile + step, tiles - 1) << 6);
        load_idx(imin(tile + 2 * step, tiles - 1) << 6);

        // ---- tensor-core GEMM on buf p ----
        float d[4][4] = {};
        unsigned aT = sAh_s + (p ? ABUFH * 2 : 0);
        #pragma unroll
        for (int ks = 0; ks < 5; ks++) {
            unsigned ar[4], b0[4], b1[4];
            ldsm4(ar, aT + aOff + ks * 32);
            ldsm4(b0, sWh_s + bOff0 + ks * 32);
            ldsm4(b1, sWh_s + bOff1 + ks * 32);
            mma16816(d[0], ar[0], ar[1], ar[2], ar[3], b0[0], b0[2]);
            mma16816(d[1], ar[0], ar[1], ar[2], ar[3], b0[1], b0[3]);
            mma16816(d[2], ar[0], ar[1], ar[2], ar[3], b1[0], b1[2]);
            mma16816(d[3], ar[0], ar[1], ar[2], ar[3], b1[1], b1[3]);
        }

        __syncthreads();   // prior epilogue readers done; sOut free; mma readers done

        // ---- fragment store -> sOut; stage next tile -> sA[p^1] ----
        {
            int fr = m0 + (l >> 2);
            int fc = nbw + 2 * (l & 3);
            #pragma unroll
            for (int nt = 0; nt < 4; nt++) {
                *(float2*)(sOut + fr * SOUT + fc + nt * 8)       = make_float2(d[nt][0], d[nt][1]);
                *(float2*)(sOut + (fr + 8) * SOUT + fc + nt * 8) = make_float2(d[nt][2], d[nt][3]);
            }
        }
        store_tile(sAh + (p ^ 1) * ABUFH, sBid + (p ^ 1) * 64);
        __syncthreads();   // sOut ready; sA[p^1] ready

        // ---- epilogue: FiLM + relu, coalesced stores ----
        const int* bb = sBid + p * 64;
        #pragma unroll
        for (int half = 0; half < 2; half++) {
            int e  = half ? el1 : el0;
            int ge = base + e;
            if (ge >= E) continue;
            int bid = bb[e];
            const float* gb = g_gb + bid * (2 * ED);
            float4 gma = *(const float4*)(gb + sub * 8);
            float4 gmb = *(const float4*)(gb + sub * 8 + 4);
            float4 bta = *(const float4*)(gb + ED + sub * 8);
            float4 btb = *(const float4*)(gb + ED + sub * 8 + 4);
            float4 xa = *(float4*)(sOut + e * SOUT + sub * 8);
            float4 xb = *(float4*)(sOut + e * SOUT + sub * 8 + 4);
            float4 oa, ob;
            oa.x = fmaxf(fmaf(xa.x + bgxa.x, gma.x, bta.x), 0.0f);
            oa.y = fmaxf(fmaf(xa.y + bgxa.y, gma.y, bta.y), 0.0f);
            oa.z = fmaxf(fmaf(xa.z + bgxa.z, gma.z, bta.z), 0.0f);
            oa.w = fmaxf(fmaf(xa.w + bgxa.w, gma.w, bta.w), 0.0f);
            ob.x = fmaxf(fmaf(xb.x + bgxb.x, gmb.x, btb.x), 0.0f);
            ob.y = fmaxf(fmaf(xb.y + bgxb.y, gmb.y, btb.y), 0.0f);
            ob.z = fmaxf(fmaf(xb.z + bgxb.z, gmb.z, btb.z), 0.0f);
            ob.w = fmaxf(fmaf(xb.w + bgxb.w, gmb.w, btb.w), 0.0f);
            float4* op = (float4*)(out + (size_t)ge * ED + sub * 8);
            op[0] = oa; op[1] = ob;
        }
        p ^= 1;
    }
}

// ---------------- Launch ---------------------------------------------------
extern "C" void kernel_launch(void* const* d_in, const int* in_sizes, int n_in,
                              void* d_out, int out_size) {
    const float* nf   = (const float*)d_in[0];
    const int*   eidx = (const int*)d_in[1];
    const float* egeo = (const float*)d_in[2];
    const float* cond = (const float*)d_in[3];
    const int*   ebid = (const int*)d_in[4];
    const float* Wn   = (const float*)d_in[5];
    const float* bn   = (const float*)d_in[6];
    const float* Wg   = (const float*)d_in[7];
    const float* bg   = (const float*)d_in[8];
    const float* Wc   = (const float*)d_in[9];
    const float* bc   = (const float*)d_in[10];
    const float* Wx   = (const float*)d_in[11];

    int N = in_sizes[0] / ND;
    int E = in_sizes[2] / GD;
    int B = in_sizes[3] / CD;

    int smem_np = (32 * WROW + 2 * ABUF) * 4;                         // 69632 B
    int smem_eg = (64 * SAH + 2 * ABUFH) * 2 + 64 * SOUT * 4 + 2 * 64 * 4;  // 51712 B
    cudaFuncSetAttribute(setup_nproj_kernel, cudaFuncAttributeMaxDynamicSharedMemorySize, smem_np);
    cudaFuncSetAttribute(edge_kernel,        cudaFuncAttributeMaxDynamicSharedMemorySize, smem_eg);

    int grid = 296;   // 2 blocks/SM on 148 SMs
    setup_nproj_kernel<<<grid, 256, smem_np>>>(nf, Wn, bn, N, Wx, Wg, bg, cond, Wc, bc, B);

    int etiles = (E + 63) >> 6;
    int egrid  = etiles < grid ? etiles : grid;
    edge_kernel<<<egrid, 256, smem_eg>>>(eidx, egeo, ebid, (float*)d_out, E);
}

// round 16
// speedup vs baseline: 2.8176x; 1.1522x over previous
#include <cuda_runtime.h>
#include <cuda_fp16.h>

#define ND 64
#define ED 64
#define GD 8
#define GO 32
#define CD 512
#define KJ 72          // folded join K = ED + GD
#define KP 80          // padded K for fp16 mma (multiple of 16)
#define MAXN 100000
#define MAXB 64

// fp32 nproj GEMM
#define SJ   100
#define WROW 144
#define ABUF (64 * SJ)

// fp16 edge GEMM
#define SAH   88           // A smem row stride in halves (ldmatrix conflict-free)
#define ABUFH (64 * SAH)   // one A buffer in halves
#define SOUT  68           // sOut row stride in floats

__device__ __align__(16) __half g_nproj[MAXN * ED];  // fp16: 12.8 MB, row = 128 B
__device__ __align__(16) __half g_gbh[MAXB * 2 * ED];// fp16 FiLM: [b][gamma|beta], 256 B/row
__device__ float g_wfold[KJ * ED];
__device__ float g_bgx[ED];
__device__ __align__(16) __half g_wfoldh[64 * KP];   // [n][k] fp16, k>=72 zero

// ---------------- helpers --------------------------------------------------
static __device__ __forceinline__ void fma2(unsigned long long& d,
                                            unsigned long long a,
                                            unsigned long long b) {
    asm("fma.rn.f32x2 %0, %1, %2, %0;" : "+l"(d) : "l"(a), "l"(b));
}
static __device__ __forceinline__ void unpack2(unsigned long long v, float& lo, float& hi) {
    asm("mov.b64 {%0, %1}, %2;" : "=f"(lo), "=f"(hi) : "l"(v));
}
static __device__ __forceinline__ int woff(int v) { return v * 2 + ((v >> 4) << 2); }
static __device__ __forceinline__ int imin(int a, int b) { return a < b ? a : b; }

static __device__ __forceinline__ void fma_kpair(unsigned long long* acc4,
                                                 ulonglong2 a,
                                                 ulonglong2 w0a, ulonglong2 w0b,
                                                 ulonglong2 w1a, ulonglong2 w1b) {
    fma2(acc4[0], a.x, w0a.x); fma2(acc4[1], a.x, w0a.y);
    fma2(acc4[2], a.x, w0b.x); fma2(acc4[3], a.x, w0b.y);
    fma2(acc4[0], a.y, w1a.x); fma2(acc4[1], a.y, w1a.y);
    fma2(acc4[2], a.y, w1b.x); fma2(acc4[3], a.y, w1b.y);
}
static __device__ __forceinline__ unsigned pack_h2(float x, float y) {
    __half2 h = __floats2half2_rn(x, y);
    return *(unsigned*)&h;
}
static __device__ __forceinline__ unsigned hmul2u(unsigned a, unsigned b) {
    __half2 r = __hmul2(*(__half2*)&a, *(__half2*)&b);
    return *(unsigned*)&r;
}
static __device__ __forceinline__ void ldsm4(unsigned* r, unsigned addr) {
    asm volatile("ldmatrix.sync.aligned.m8n8.x4.shared.b16 {%0,%1,%2,%3}, [%4];"
                 : "=r"(r[0]), "=r"(r[1]), "=r"(r[2]), "=r"(r[3]) : "r"(addr));
}
static __device__ __forceinline__ void mma16816(float* d,
                                                unsigned a0, unsigned a1, unsigned a2, unsigned a3,
                                                unsigned b0, unsigned b1) {
    asm volatile("mma.sync.aligned.m16n8k16.row.col.f32.f16.f16.f32 "
                 "{%0,%1,%2,%3}, {%4,%5,%6,%7}, {%8,%9}, {%0,%1,%2,%3};"
                 : "+f"(d[0]), "+f"(d[1]), "+f"(d[2]), "+f"(d[3])
                 : "r"(a0), "r"(a1), "r"(a2), "r"(a3), "r"(b0), "r"(b1));
}

// ---------------------------------------------------------------------------
// Kernel 1: setup (film blocks 0..B-1, prep block B) + pipelined n_proj (all)
// n_proj computed in fp32, stored as fp16. FiLM table stored as fp16.
// ---------------------------------------------------------------------------
__global__ void __launch_bounds__(256, 2)
setup_nproj_kernel(const float* __restrict__ nf,
                   const float* __restrict__ Wn,
                   const float* __restrict__ bn,
                   int N,
                   const float* __restrict__ Wx,
                   const float* __restrict__ Wg,
                   const float* __restrict__ bg,
                   const float* __restrict__ cond,
                   const float* __restrict__ Wc,
                   const float* __restrict__ bc,
                   int B) {
    extern __shared__ __align__(16) char smem_raw[];
    int t = threadIdx.x;

    if ((int)blockIdx.x < B) {
        float* sc  = (float*)smem_raw;
        float* red = sc + CD;
        int b = blockIdx.x;
        for (int i = t; i < CD; i += 256) sc[i] = cond[b * CD + i];
        __syncthreads();
        int j  = t & 127;
        int kb = (t >> 7) * 256;
        float a0 = 0, a1 = 0, a2 = 0, a3 = 0;
        #pragma unroll 4
        for (int k = 0; k < 256; k += 4) {
            a0 = fmaf(sc[kb + k + 0], Wc[(kb + k + 0) * (2 * ED) + j], a0);
            a1 = fmaf(sc[kb + k + 1], Wc[(kb + k + 1) * (2 * ED) + j], a1);
            a2 = fmaf(sc[kb + k + 2], Wc[(kb + k + 2) * (2 * ED) + j], a2);
            a3 = fmaf(sc[kb + k + 3], Wc[(kb + k + 3) * (2 * ED) + j], a3);
        }
        red[t] = (a0 + a1) + (a2 + a3);
        __syncthreads();
        if (t < 128) {
            float acc = red[t] + red[t + 128] + bc[j];
            if (j < ED) acc += 1.0f;
            g_gbh[b * (2 * ED) + j] = __float2half_rn(acc);
        }
    } else if ((int)blockIdx.x == B) {
        for (int idx = t; idx < KJ * ED; idx += 256) {
            int k = idx >> 6, j = idx & 63;
            float v;
            if (k < ED) {
                v = Wx[k * ED + j];
            } else {
                int g = k - ED;
                v = 0.0f;
                #pragma unroll 8
                for (int m = 0; m < GO; m++)
                    v = fmaf(Wg[g * GO + m], Wx[(ED + m) * ED + j], v);
            }
            g_wfold[idx] = v;
        }
        for (int j = t; j < ED; j += 256) {
            float v = 0.0f;
            #pragma unroll 8
            for (int m = 0; m < GO; m++)
                v = fmaf(bg[m], Wx[(ED + m) * ED + j], v);
            g_bgx[j] = v;
        }
        __syncthreads();
        // fp16 transposed padded copy for the edge kernel's tensor-core GEMM
        for (int i = t; i < 64 * KP; i += 256) {
            int n = i / KP, k = i - n * KP;
            float v = (k < KJ) ? g_wfold[k * ED + n] : 0.0f;
            g_wfoldh[n * KP + k] = __float2half_rn(v);
        }
    }
    __syncthreads();   // smem reuse barrier

    // ---- n_proj phase (fp32 f32x2, double-buffered; fp16 output) ----
    float* sWp = (float*)smem_raw;             // [32][WROW]
    float* sA  = sWp + 32 * WROW;              // [2][64][SJ]

    for (int i = t; i < 32 * 64; i += 256) {
        int k2 = i >> 6, c = i & 63;
        float lo = Wn[(2 * k2) * ED + c];
        float hi = Wn[(2 * k2 + 1) * ED + c];
        float* dst = sWp + k2 * WROW + woff(c);
        dst[0] = lo; dst[1] = hi;
    }

    const int cidx = t & 15, m = t >> 4;
    const int cg   = cidx * 4;
    const int wcol = woff(cg);
    const int swz  = (m >> 1) & 3;
    const int sub  = t & 7;
    const int el0  = t >> 3;
    const int el1  = 32 + el0;
    const int rs0  = (el0 >> 3) & 3, rs1 = (el1 >> 3) & 3;
    const int c0s  = sub >> 1, c1s = 4 + (sub >> 1), osub = 4 * (sub & 1);
    float4 bn4 = *(const float4*)(bn + cg);

    int tiles = (N + 63) >> 6;
    int step  = gridDim.x;
    int Nc    = N - 1;

    float4 st[4];
    auto load_rows = [&](int nb) {
        int g0 = imin(nb + el0, Nc), g1 = imin(nb + el1, Nc);
        const float4* rp0 = (const float4*)(nf + (size_t)g0 * ND);
        const float4* rp1 = (const float4*)(nf + (size_t)g1 * ND);
        st[0] = rp0[sub]; st[1] = rp0[sub + 8];
        st[2] = rp1[sub]; st[3] = rp1[sub + 8];
    };
    auto store_rows = [&](float* buf) {
        *(float4*)(buf + el0 * SJ + ((c0s ^ rs0) << 3) + osub) = st[0];
        *(float4*)(buf + el0 * SJ + ((c1s ^ rs0) << 3) + osub) = st[1];
        *(float4*)(buf + el1 * SJ + ((c0s ^ rs1) << 3) + osub) = st[2];
        *(float4*)(buf + el1 * SJ + ((c1s ^ rs1) << 3) + osub) = st[3];
    };

    if ((int)blockIdx.x < tiles) {
        load_rows((int)blockIdx.x << 6);
        store_rows(sA);
    }
    __syncthreads();

    int p = 0;
    for (int tile = blockIdx.x; tile < tiles; tile += step) {
        int base = tile << 6;
        load_rows(imin(tile + step, tiles - 1) << 6);

        unsigned long long acc[4][4] = {};
        const float* aB = sA + p * ABUF + (m * 4) * SJ;
        #pragma unroll
        for (int c = 0; c < 8; c++) {
            int pc = (c ^ swz) << 3;
            #pragma unroll
            for (int half = 0; half < 2; half++) {
                int k2b = c * 4 + half * 2;
                ulonglong2 a0 = *(const ulonglong2*)(aB + 0 * SJ + pc + half * 4);
                ulonglong2 a1 = *(const ulonglong2*)(aB + 1 * SJ + pc + half * 4);
                ulonglong2 a2 = *(const ulonglong2*)(aB + 2 * SJ + pc + half * 4);
                ulonglong2 a3 = *(const ulonglong2*)(aB + 3 * SJ + pc + half * 4);
                const float* w0 = sWp + k2b * WROW + wcol;
                const float* w1 = w0 + WROW;
                ulonglong2 w0a = *(const ulonglong2*)(w0);
                ulonglong2 w0b = *(const ulonglong2*)(w0 + 4);
                ulonglong2 w1a = *(const ulonglong2*)(w1);
                ulonglong2 w1b = *(const ulonglong2*)(w1 + 4);
                fma_kpair(acc[0], a0, w0a, w0b, w1a, w1b);
                fma_kpair(acc[1], a1, w0a, w0b, w1a, w1b);
                fma_kpair(acc[2], a2, w0a, w0b, w1a, w1b);
                fma_kpair(acc[3], a3, w0a, w0b, w1a, w1b);
            }
        }

        #pragma unroll
        for (int i = 0; i < 4; i++) {
            int gn = base + m * 4 + i;
            if (gn >= N) continue;
            float l0, h0, l1, h1, l2, h2, l3, h3;
            unpack2(acc[i][0], l0, h0);
            unpack2(acc[i][1], l1, h1);
            unpack2(acc[i][2], l2, h2);
            unpack2(acc[i][3], l3, h3);
            uint2 u;
            u.x = pack_h2(l0 + h0 + bn4.x, l1 + h1 + bn4.y);
            u.y = pack_h2(l2 + h2 + bn4.z, l3 + h3 + bn4.w);
            *(uint2*)(g_nproj + (size_t)gn * ED + cg) = u;
        }

        store_rows(sA + (p ^ 1) * ABUF);
        __syncthreads();
        p ^= 1;
    }
}

// ---------------------------------------------------------------------------
// Kernel 2: fused edge kernel — fp16 gather + fp16 tensor-core GEMM
// Tile 64 edges x 64 cols x K80. 8 warps: each m16 x n32.
// B fragments for the low n16 are hoisted into registers (tile-invariant).
// ---------------------------------------------------------------------------
__global__ void __launch_bounds__(256, 2)
edge_kernel(const int* __restrict__ eidx,
            const float* __restrict__ egeo,
            const int* __restrict__ ebid,
            float* __restrict__ out,
            int E) {
    extern __shared__ __align__(16) char smem_raw[];
    __half* sWh  = (__half*)smem_raw;            // [64 n][SAH]
    __half* sAh  = sWh + 64 * SAH;               // [2][64 edge][SAH]
    float*  sOut = (float*)(sAh + 2 * ABUFH);    // [64][SOUT]
    int*    sBid = (int*)(sOut + 64 * SOUT);     // [2][64]

    int t = threadIdx.x;

    // zero A buffers once (pad seg must not contain NaN/Inf bit garbage)
    for (int i = t; i < 2 * ABUFH / 8; i += 256)
        ((uint4*)sAh)[i] = make_uint4(0, 0, 0, 0);
    // stage W fp16 [n][k] with pad zeros
    for (int i = t; i < 64 * (KP / 8); i += 256) {
        int n = i / 10, seg = i - n * 10;
        uint4 v = *(const uint4*)(g_wfoldh + n * KP + seg * 8);
        *(uint4*)(sWh + n * SAH + seg * 8) = v;
    }

    const int w = t >> 5, l = t & 31;
    const int m0  = (w & 3) * 16;
    const int nbw = (w >> 2) * 32;
    const int sub = t & 7;
    const int el0 = t >> 3;
    const int el1 = 32 + el0;
    const int elg = t >> 1, hg = t & 1;          // geo task (t<128)

    unsigned sWh_s = (unsigned)__cvta_generic_to_shared(sWh);
    unsigned sAh_s = (unsigned)__cvta_generic_to_shared(sAh);
    const unsigned aOff  = ((m0 + (l & 15)) * SAH + ((l >> 4) << 3)) * 2;
    const unsigned bOff0 = ((nbw + (((l >> 3) & 1) << 3) + (l & 7)) * SAH + ((l >> 4) << 3)) * 2;
    const unsigned bOff1 = bOff0 + 16 * SAH * 2;

    float4 bgxa = *(const float4*)(g_bgx + sub * 8);
    float4 bgxb = *(const float4*)(g_bgx + sub * 8 + 4);

    int tiles = (E + 63) >> 6;
    int step  = gridDim.x;
    int Ec    = E - 1;

    uint4 su[4];                   // fp16 rows: src0, dst0, src1, dst1
    float4 geoS;
    int ns0, nd0, ns1, nd1;
    int bidS = 0, nbid = 0;

    auto load_idx = [&](int nb) {
        int h0 = imin(nb + el0, Ec), h1 = imin(nb + el1, Ec);
        ns0 = eidx[h0];
        nd0 = eidx[E + h0];
        ns1 = eidx[h1];
        nd1 = eidx[E + h1];
        if (t < 64) nbid = ebid[imin(nb + t, Ec)];
    };
    auto load_rows = [&](int nb) {
        // one contiguous uint4 per lane: 8 lanes cover the full 128 B row
        su[0] = ((const uint4*)(g_nproj + (size_t)ns0 * ED))[sub];
        su[1] = ((const uint4*)(g_nproj + (size_t)nd0 * ED))[sub];
        su[2] = ((const uint4*)(g_nproj + (size_t)ns1 * ED))[sub];
        su[3] = ((const uint4*)(g_nproj + (size_t)nd1 * ED))[sub];
        if (t < 128) {
            int ge = imin(nb + elg, Ec);
            geoS = *(const float4*)(egeo + (size_t)ge * GD + 4 * hg);
        }
        bidS = nbid;
    };
    auto store_tile = [&](__half* buf, int* bbid) {
        uint4 u0, u1;
        u0.x = hmul2u(su[0].x, su[1].x); u0.y = hmul2u(su[0].y, su[1].y);
        u0.z = hmul2u(su[0].z, su[1].z); u0.w = hmul2u(su[0].w, su[1].w);
        u1.x = hmul2u(su[2].x, su[3].x); u1.y = hmul2u(su[2].y, su[3].y);
        u1.z = hmul2u(su[2].z, su[3].z); u1.w = hmul2u(su[2].w, su[3].w);
        *(uint4*)(buf + el0 * SAH + sub * 8) = u0;
        *(uint4*)(buf + el1 * SAH + sub * 8) = u1;
        if (t < 128) {
            uint2 g2;
            g2.x = pack_h2(geoS.x, geoS.y);
            g2.y = pack_h2(geoS.z, geoS.w);
            *(uint2*)(buf + elg * SAH + 64 + 4 * hg) = g2;
        }
        if (t < 64) bbid[t] = bidS;
    };

    {   // prologue
        int nb0 = imin((int)blockIdx.x, tiles - 1) << 6;
        load_idx(nb0);
        load_rows(nb0);
        // barrier: one-time zeroing of sAh must complete before tile-0 staging;
        // also orders sWh staging before the B-fragment hoist below
        __syncthreads();
        store_tile(sAh, sBid);
        load_idx(imin((int)blockIdx.x + step, tiles - 1) << 6);
    }

    // hoist low-n16 B fragments (tile-invariant W) into registers
    unsigned bh[5][4];
    #pragma unroll
    for (int ks = 0; ks < 5; ks++)
        ldsm4(bh[ks], sWh_s + bOff0 + ks * 32);

    __syncthreads();

    int p = 0;
    for (int tile = blockIdx.x; tile < tiles; tile += step) {
        int base = tile << 6;
        load_rows(imin(tile + step, tiles - 1) << 6);
        load_idx(imin(tile + 2 * step, tiles - 1) << 6);

        // ---- tensor-core GEMM on buf p ----
        float d[4][4] = {};
        unsigned aT = sAh_s + (p ? ABUFH * 2 : 0);
        #pragma unroll
        for (int ks = 0; ks < 5; ks++) {
            unsigned ar[4], b1[4];
            ldsm4(ar, aT + aOff + ks * 32);
            ldsm4(b1, sWh_s + bOff1 + ks * 32);
            mma16816(d[0], ar[0], ar[1], ar[2], ar[3], bh[ks][0], bh[ks][2]);
            mma16816(d[1], ar[0], ar[1], ar[2], ar[3], bh[ks][1], bh[ks][3]);
            mma16816(d[2], ar[0], ar[1], ar[2], ar[3], b1[0], b1[2]);
            mma16816(d[3], ar[0], ar[1], ar[2], ar[3], b1[1], b1[3]);
        }

        __syncthreads();   // prior epilogue readers done; sOut free; mma readers done

        // ---- fragment store -> sOut; stage next tile -> sA[p^1] ----
        {
            int fr = m0 + (l >> 2);
            int fc = nbw + 2 * (l & 3);
            #pragma unroll
            for (int nt = 0; nt < 4; nt++) {
                *(float2*)(sOut + fr * SOUT + fc + nt * 8)       = make_float2(d[nt][0], d[nt][1]);
                *(float2*)(sOut + (fr + 8) * SOUT + fc + nt * 8) = make_float2(d[nt][2], d[nt][3]);
            }
        }
        store_tile(sAh + (p ^ 1) * ABUFH, sBid + (p ^ 1) * 64);
        __syncthreads();   // sOut ready; sA[p^1] ready

        // ---- epilogue: FiLM (fp16 table) + relu, coalesced stores ----
        const int* bb = sBid + p * 64;
        #pragma unroll
        for (int half = 0; half < 2; half++) {
            int e  = half ? el1 : el0;
            int ge = base + e;
            if (ge >= E) continue;
            int bid = bb[e];
            const __half* gbh = g_gbh + bid * (2 * ED);
            uint4 gu = *(const uint4*)(gbh + sub * 8);        // gamma cols sub*8..+7
            uint4 bu = *(const uint4*)(gbh + ED + sub * 8);   // beta  cols sub*8..+7
            const __half2* gh = (const __half2*)&gu;
            const __half2* bh2 = (const __half2*)&bu;
            float2 g0 = __half22float2(gh[0]), g1 = __half22float2(gh[1]);
            float2 g2 = __half22float2(gh[2]), g3 = __half22float2(gh[3]);
            float2 f0 = __half22float2(bh2[0]), f1 = __half22float2(bh2[1]);
            float2 f2 = __half22float2(bh2[2]), f3 = __half22float2(bh2[3]);
            float4 xa = *(float4*)(sOut + e * SOUT + sub * 8);
            float4 xb = *(float4*)(sOut + e * SOUT + sub * 8 + 4);
            float4 oa, ob;
            oa.x = fmaxf(fmaf(xa.x + bgxa.x, g0.x, f0.x), 0.0f);
            oa.y = fmaxf(fmaf(xa.y + bgxa.y, g0.y, f0.y), 0.0f);
            oa.z = fmaxf(fmaf(xa.z + bgxa.z, g1.x, f1.x), 0.0f);
            oa.w = fmaxf(fmaf(xa.w + bgxa.w, g1.y, f1.y), 0.0f);
            ob.x = fmaxf(fmaf(xb.x + bgxb.x, g2.x, f2.x), 0.0f);
            ob.y = fmaxf(fmaf(xb.y + bgxb.y, g2.y, f2.y), 0.0f);
            ob.z = fmaxf(fmaf(xb.z + bgxb.z, g3.x, f3.x), 0.0f);
            ob.w = fmaxf(fmaf(xb.w + bgxb.w, g3.y, f3.y), 0.0f);
            float4* op = (float4*)(out + (size_t)ge * ED + sub * 8);
            op[0] = oa; op[1] = ob;
        }
        p ^= 1;
    }
}

// ---------------- Launch ---------------------------------------------------
extern "C" void kernel_launch(void* const* d_in, const int* in_sizes, int n_in,
                              void* d_out, int out_size) {
    const float* nf   = (const float*)d_in[0];
    const int*   eidx = (const int*)d_in[1];
    const float* egeo = (const float*)d_in[2];
    const float* cond = (const float*)d_in[3];
    const int*   ebid = (const int*)d_in[4];
    const float* Wn   = (const float*)d_in[5];
    const float* bn   = (const float*)d_in[6];
    const float* Wg   = (const float*)d_in[7];
    const float* bg   = (const float*)d_in[8];
    const float* Wc   = (const float*)d_in[9];
    const float* bc   = (const float*)d_in[10];
    const float* Wx   = (const float*)d_in[11];

    int N = in_sizes[0] / ND;
    int E = in_sizes[2] / GD;
    int B = in_sizes[3] / CD;

    int smem_np = (32 * WROW + 2 * ABUF) * 4;                         // 69632 B
    int smem_eg = (64 * SAH + 2 * ABUFH) * 2 + 64 * SOUT * 4 + 2 * 64 * 4;  // 51712 B
    cudaFuncSetAttribute(setup_nproj_kernel, cudaFuncAttributeMaxDynamicSharedMemorySize, smem_np);
    cudaFuncSetAttribute(edge_kernel,        cudaFuncAttributeMaxDynamicSharedMemorySize, smem_eg);

    int grid = 296;   // 2 blocks/SM on 148 SMs
    setup_nproj_kernel<<<grid, 256, smem_np>>>(nf, Wn, bn, N, Wx, Wg, bg, cond, Wc, bc, B);

    int etiles = (E + 63) >> 6;
    int egrid  = etiles < grid ? etiles : grid;
    edge_kernel<<<egrid, 256, smem_eg>>>(eidx, egeo, ebid, (float*)d_out, E);
}